// round 1
// baseline (speedup 1.0000x reference)
#include <cuda_runtime.h>
#include <cuda_bf16.h>

#define B_DIM 4
#define T_DIM 256
#define S_DIM 256
#define D_DIM 512

// ---------------- scratch (no allocation allowed) ----------------
__device__ float g_wq[B_DIM * T_DIM * D_DIM];     // 2 MB
__device__ float g_uh[B_DIM * S_DIM * D_DIM];     // 2 MB
__device__ float g_score[B_DIM * T_DIM * S_DIM];  // 1 MB
__device__ float g_attn[B_DIM * T_DIM * S_DIM];   // 1 MB
__device__ float g_mix[B_DIM * T_DIM * D_DIM];    // 2 MB

__device__ __forceinline__ float tanh_fast(float x) {
    float y;
    asm("tanh.approx.f32 %0, %1;" : "=f"(y) : "f"(x));
    return y;
}

// ---------------- generic 64x64 FFMA GEMM ----------------
// C[M,N] = A[M,K] (row-major) * B[K,N] (row-major) [+ bias[n]] [+ C]
// Requires M%64==0, N%64==0, K%16==0. Batched via blockIdx.z with strides.
__global__ __launch_bounds__(256) void gemm64(
    const float* __restrict__ A, const float* __restrict__ B,
    float* __restrict__ C, int M, int N, int K,
    const float* __restrict__ bias, int accumulate,
    long sA, long sB, long sC)
{
    A += (long)blockIdx.z * sA;
    B += (long)blockIdx.z * sB;
    C += (long)blockIdx.z * sC;

    __shared__ float As[16][68];   // transposed A tile, padded (272B rows keep 16B align)
    __shared__ float Bs[16][64];

    const int tid = threadIdx.x;
    const int tx = tid % 16;        // n direction
    const int ty = tid / 16;        // m direction
    const int m0 = blockIdx.y * 64;
    const int n0 = blockIdx.x * 64;

    float acc[4][4] = {};

    for (int k0 = 0; k0 < K; k0 += 16) {
        // Load A tile: 64 rows x 16 k, each thread one float4 along k.
        {
            int row = tid >> 2;            // 0..63
            int kc  = (tid & 3) * 4;       // 0,4,8,12
            float4 a = *(const float4*)&A[(long)(m0 + row) * K + k0 + kc];
            As[kc + 0][row] = a.x;
            As[kc + 1][row] = a.y;
            As[kc + 2][row] = a.z;
            As[kc + 3][row] = a.w;
            // Load B tile: 16 rows x 64 n, each thread one float4 along n.
            int brow = tid >> 4;           // 0..15
            int bn   = (tid & 15) * 4;     // 0..60
            *(float4*)&Bs[brow][bn] = *(const float4*)&B[(long)(k0 + brow) * N + n0 + bn];
        }
        __syncthreads();

        #pragma unroll
        for (int k = 0; k < 16; k++) {
            float4 a4 = *(const float4*)&As[k][ty * 4];
            float4 b4 = *(const float4*)&Bs[k][tx * 4];
            float av[4] = {a4.x, a4.y, a4.z, a4.w};
            float bv[4] = {b4.x, b4.y, b4.z, b4.w};
            #pragma unroll
            for (int i = 0; i < 4; i++)
                #pragma unroll
                for (int j = 0; j < 4; j++)
                    acc[i][j] = fmaf(av[i], bv[j], acc[i][j]);
        }
        __syncthreads();
    }

    const int n = n0 + tx * 4;
    #pragma unroll
    for (int i = 0; i < 4; i++) {
        int m = m0 + ty * 4 + i;
        float4 o;
        o.x = acc[i][0]; o.y = acc[i][1]; o.z = acc[i][2]; o.w = acc[i][3];
        if (bias) {
            o.x += bias[n + 0]; o.y += bias[n + 1];
            o.z += bias[n + 2]; o.w += bias[n + 3];
        }
        if (accumulate) {
            float4 c = *(const float4*)&C[(long)m * N + n];
            o.x += c.x; o.y += c.y; o.z += c.z; o.w += c.w;
        }
        *(float4*)&C[(long)m * N + n] = o;
    }
}

// ---------------- score kernel: score[b,t,s] = sum_d v[d]*tanh(wq[b,t,d]+uh[b,s,d]) ----
// grid (S/16, T/16, B), 256 threads; each thread owns one (t,s) pair.
__global__ __launch_bounds__(256) void score_kernel(
    const float* __restrict__ wq, const float* __restrict__ uh,
    const float* __restrict__ v, float* __restrict__ score)
{
    const int b  = blockIdx.z;
    const int t0 = blockIdx.y * 16;
    const int s0 = blockIdx.x * 16;

    __shared__ float wq_s[16][128];
    __shared__ float uh_s[16][128];
    __shared__ float v_s[128];

    const int tid = threadIdx.x;
    const int tt  = tid >> 4;   // 0..15 -> t
    const int ss  = tid & 15;   // 0..15 -> s

    const float* wq_b = wq + ((long)b * T_DIM + t0) * D_DIM;
    const float* uh_b = uh + ((long)b * S_DIM + s0) * D_DIM;

    float acc = 0.0f;

    for (int d0 = 0; d0 < D_DIM; d0 += 128) {
        {
            int row = tid >> 4;          // 0..15
            int col = (tid & 15) * 8;    // 0..120
            *(float4*)&wq_s[row][col]     = *(const float4*)&wq_b[(long)row * D_DIM + d0 + col];
            *(float4*)&wq_s[row][col + 4] = *(const float4*)&wq_b[(long)row * D_DIM + d0 + col + 4];
            *(float4*)&uh_s[row][col]     = *(const float4*)&uh_b[(long)row * D_DIM + d0 + col];
            *(float4*)&uh_s[row][col + 4] = *(const float4*)&uh_b[(long)row * D_DIM + d0 + col + 4];
            if (tid < 32) *(float4*)&v_s[tid * 4] = *(const float4*)&v[d0 + tid * 4];
        }
        __syncthreads();

        #pragma unroll
        for (int d = 0; d < 128; d += 4) {
            float4 a = *(const float4*)&wq_s[tt][d];
            float4 u = *(const float4*)&uh_s[ss][d];
            float4 w = *(const float4*)&v_s[d];
            acc = fmaf(w.x, tanh_fast(a.x + u.x), acc);
            acc = fmaf(w.y, tanh_fast(a.y + u.y), acc);
            acc = fmaf(w.z, tanh_fast(a.z + u.z), acc);
            acc = fmaf(w.w, tanh_fast(a.w + u.w), acc);
        }
        __syncthreads();
    }

    score[((long)b * T_DIM + t0 + tt) * S_DIM + s0 + ss] = acc;
}

// ---------------- masked softmax (exact reference semantics) ----------------
// max over ALL positions; exp(score-max) * (1-mask); renormalize.
// grid = B*T blocks, 256 threads (one per s).
__global__ __launch_bounds__(256) void softmax_kernel(
    const float* __restrict__ score, const int* __restrict__ mask,
    float* __restrict__ attn, float* __restrict__ attn_out)
{
    const int row = blockIdx.x;          // b*T + t
    const int b   = row / T_DIM;
    const int s   = threadIdx.x;
    const int lane = s & 31;
    const int warp = s >> 5;

    __shared__ float red_max[8];
    __shared__ float red_sum[8];

    float sc = score[(long)row * S_DIM + s];

    float m = sc;
    #pragma unroll
    for (int o = 16; o > 0; o >>= 1) m = fmaxf(m, __shfl_xor_sync(0xffffffffu, m, o));
    if (lane == 0) red_max[warp] = m;
    __syncthreads();
    m = red_max[0];
    #pragma unroll
    for (int i = 1; i < 8; i++) m = fmaxf(m, red_max[i]);

    float keep = 1.0f - (float)mask[b * S_DIM + s];
    float e = __expf(sc - m) * keep;

    float sum = e;
    #pragma unroll
    for (int o = 16; o > 0; o >>= 1) sum += __shfl_xor_sync(0xffffffffu, sum, o);
    if (lane == 0) red_sum[warp] = sum;
    __syncthreads();
    sum = red_sum[0];
    #pragma unroll
    for (int i = 1; i < 8; i++) sum += red_sum[i];

    float a = e / sum;
    attn[(long)row * S_DIM + s] = a;
    if (attn_out) attn_out[(long)row * S_DIM + s] = a;
}

// ---------------- launch ----------------
extern "C" void kernel_launch(void* const* d_in, const int* in_sizes, int n_in,
                              void* d_out, int out_size)
{
    const float* output  = (const float*)d_in[0];
    const float* context = (const float*)d_in[1];
    const int*   mask    = (const int*)d_in[2];
    const float* Wq      = (const float*)d_in[3];
    const float* bq      = (const float*)d_in[4];
    const float* Wc      = (const float*)d_in[5];
    const float* v       = (const float*)d_in[6];
    const float* Wout    = (const float*)d_in[7];
    const float* bout    = (const float*)d_in[8];

    float *wq, *uh, *score, *attn, *mix;
    cudaGetSymbolAddress((void**)&wq,    g_wq);
    cudaGetSymbolAddress((void**)&uh,    g_uh);
    cudaGetSymbolAddress((void**)&score, g_score);
    cudaGetSymbolAddress((void**)&attn,  g_attn);
    cudaGetSymbolAddress((void**)&mix,   g_mix);

    float* out = (float*)d_out;
    const int out_elems  = B_DIM * T_DIM * D_DIM;   // 524288
    const int attn_elems = B_DIM * T_DIM * S_DIM;   // 262144
    float* attn_out = (out_size >= out_elems + attn_elems) ? (out + out_elems) : nullptr;

    const dim3 blk(256);

    // wq = output @ Wq + bq        (1024x512 @ 512x512)
    gemm64<<<dim3(8, 16, 1), blk>>>(output, Wq, wq, 1024, 512, 512, bq, 0, 0, 0, 0);
    // uh = context @ Wc            (1024x512 @ 512x512)
    gemm64<<<dim3(8, 16, 1), blk>>>(context, Wc, uh, 1024, 512, 512, nullptr, 0, 0, 0, 0);
    // score[b,t,s] = v . tanh(wq + uh)
    score_kernel<<<dim3(16, 16, 4), blk>>>(wq, uh, v, score);
    // masked softmax -> attn (also written to d_out tail)
    softmax_kernel<<<B_DIM * T_DIM, 256>>>(score, mask, attn, attn_out);
    // mix = attn @ context         (batched: 256x256 @ 256x512, 4 batches)
    gemm64<<<dim3(8, 4, 4), blk>>>(attn, context, mix, 256, 512, 256, nullptr, 0,
                                   (long)T_DIM * S_DIM, (long)S_DIM * D_DIM, (long)T_DIM * D_DIM);
    // out = mix @ Wout[0:512] + bout
    gemm64<<<dim3(8, 16, 1), blk>>>(mix, Wout, out, 1024, 512, 512, bout, 0, 0, 0, 0);
    // out += output @ Wout[512:1024]
    gemm64<<<dim3(8, 16, 1), blk>>>(output, Wout + 512 * 512, out, 1024, 512, 512, nullptr, 1, 0, 0, 0);
}

// round 4
// speedup vs baseline: 1.5711x; 1.5711x over previous
#include <cuda_runtime.h>

#define B_DIM 4
#define T_DIM 256
#define S_DIM 256
#define D_DIM 512

// ---------------- scratch (no allocation allowed) ----------------
__device__ float g_wq[B_DIM * T_DIM * D_DIM];     // 2 MB
__device__ float g_uh[B_DIM * S_DIM * D_DIM];     // 2 MB
__device__ float g_score[B_DIM * T_DIM * S_DIM];  // 1 MB
__device__ float g_attn[B_DIM * T_DIM * S_DIM];   // 1 MB
__device__ float g_mix[B_DIM * T_DIM * D_DIM];    // 2 MB

__device__ __forceinline__ float tanh_fast(float x) {
    float y;
    asm("tanh.approx.f32 %0, %1;" : "=f"(y) : "f"(x));
    return y;
}

// ---------------- GEMM: 64x64 tile, 128 threads, 8x4 micro, double buffered ----
// C[M,N] = [A | A2][M, Ktot] @ Bm[Ktot, N] (+ bias[n]).
// A covers k in [0, Ka) with row stride Ka; A2 (optional) covers [Ka, Ktot)
// with row stride (Ktot - Ka). Batched over blockIdx.z via element strides.
__global__ __launch_bounds__(128) void gemm_tile(
    const float* __restrict__ A, const float* __restrict__ A2,
    const float* __restrict__ Bm, float* __restrict__ C,
    int N, int Ka, int Ktot, const float* __restrict__ bias,
    long sA, long sB, long sC)
{
    A  += (long)blockIdx.z * sA;
    Bm += (long)blockIdx.z * sB;
    C  += (long)blockIdx.z * sC;

    __shared__ float As[2][16][68];  // transposed A tile [k][m], stride 68 (16B aligned)
    __shared__ float Bs[2][16][64];

    const int tid  = threadIdx.x;
    const int tx   = tid & 15;        // n micro
    const int ty   = tid >> 4;        // m micro (8 rows each)
    const int m0   = blockIdx.y * 64;
    const int n0   = blockIdx.x * 64;
    const int arow = tid >> 1;        // 0..63
    const int akc  = (tid & 1) * 8;   // 0 or 8
    const int brow = tid >> 4;        // 0..7
    const int bcol = (tid & 15) * 4;  // 0..60

    const int KT  = Ktot >> 4;
    const int KaT = Ka >> 4;
    const int Kb  = Ktot - Ka;

    float4 a0p, a1p, b0p, b1p;

#define LDG_TILE(kt) {                                                        \
        int _gk = (kt) << 4;                                                  \
        const float* _Ap;                                                     \
        if (A2 && (kt) >= KaT)                                                \
            _Ap = A2 + (long)(m0 + arow) * Kb + (_gk - Ka) + akc;             \
        else                                                                  \
            _Ap = A  + (long)(m0 + arow) * Ka + _gk + akc;                    \
        a0p = *(const float4*)_Ap;                                            \
        a1p = *(const float4*)(_Ap + 4);                                      \
        const float* _Bp = Bm + (long)_gk * N + n0 + bcol;                    \
        b0p = *(const float4*)(_Bp + (long)brow * N);                         \
        b1p = *(const float4*)(_Bp + (long)(brow + 8) * N);                   \
    }

#define STS_TILE(bf) {                                                        \
        As[bf][akc + 0][arow] = a0p.x;                                        \
        As[bf][akc + 1][arow] = a0p.y;                                        \
        As[bf][akc + 2][arow] = a0p.z;                                        \
        As[bf][akc + 3][arow] = a0p.w;                                        \
        As[bf][akc + 4][arow] = a1p.x;                                        \
        As[bf][akc + 5][arow] = a1p.y;                                        \
        As[bf][akc + 6][arow] = a1p.z;                                        \
        As[bf][akc + 7][arow] = a1p.w;                                        \
        *(float4*)&Bs[bf][brow][bcol]     = b0p;                              \
        *(float4*)&Bs[bf][brow + 8][bcol] = b1p;                              \
    }

    LDG_TILE(0);
    STS_TILE(0);
    __syncthreads();

    float acc[8][4] = {};

    for (int kt = 0; kt < KT; kt++) {
        const int buf = kt & 1;
        if (kt + 1 < KT) LDG_TILE(kt + 1);

        #pragma unroll
        for (int k = 0; k < 16; k++) {
            float4 a0 = *(const float4*)&As[buf][k][ty * 8];
            float4 a1 = *(const float4*)&As[buf][k][ty * 8 + 4];
            float4 b  = *(const float4*)&Bs[buf][k][tx * 4];
            float av[8] = {a0.x, a0.y, a0.z, a0.w, a1.x, a1.y, a1.z, a1.w};
            float bv[4] = {b.x, b.y, b.z, b.w};
            #pragma unroll
            for (int i = 0; i < 8; i++)
                #pragma unroll
                for (int j = 0; j < 4; j++)
                    acc[i][j] = fmaf(av[i], bv[j], acc[i][j]);
        }

        if (kt + 1 < KT) STS_TILE(buf ^ 1);  // other buffer: last read of it ended at prev sync
        __syncthreads();
    }

    const int n = n0 + tx * 4;
    #pragma unroll
    for (int i = 0; i < 8; i++) {
        int m = m0 + ty * 8 + i;
        float4 o;
        o.x = acc[i][0]; o.y = acc[i][1]; o.z = acc[i][2]; o.w = acc[i][3];
        if (bias) {
            o.x += bias[n + 0]; o.y += bias[n + 1];
            o.z += bias[n + 2]; o.w += bias[n + 3];
        }
        *(float4*)&C[(long)m * N + n] = o;
    }
#undef LDG_TILE
#undef STS_TILE
}

// ---------------- score kernel: score[b,t,s] = sum_d v[d]*tanh(wq[b,t,d]+uh[b,s,d]) ----
// 32x32 (t,s) tile per block, 2x2 micro per thread, transposed [d][row] smem.
__global__ __launch_bounds__(256) void score_kernel(
    const float* __restrict__ wq, const float* __restrict__ uh,
    const float* __restrict__ v, float* __restrict__ score)
{
    const int b  = blockIdx.z;
    const int t0 = blockIdx.y * 32;
    const int s0 = blockIdx.x * 32;

    __shared__ float wq_s[64][34];  // [d][t], d-chunk 64
    __shared__ float uh_s[64][34];  // [d][s]
    __shared__ float v_s[64];

    const int tid  = threadIdx.x;
    const int tt   = tid >> 4;   // 0..15 -> t pair
    const int ss   = tid & 15;   // 0..15 -> s pair
    const int lrow = tid >> 3;   // 0..31 load row
    const int lcol = (tid & 7) * 8;

    const float* wq_b = wq + ((long)b * T_DIM + t0) * D_DIM;
    const float* uh_b = uh + ((long)b * S_DIM + s0) * D_DIM;

    float acc00 = 0.f, acc01 = 0.f, acc10 = 0.f, acc11 = 0.f;

    for (int d0 = 0; d0 < D_DIM; d0 += 64) {
        float4 w0 = *(const float4*)&wq_b[(long)lrow * D_DIM + d0 + lcol];
        float4 w1 = *(const float4*)&wq_b[(long)lrow * D_DIM + d0 + lcol + 4];
        float4 u0 = *(const float4*)&uh_b[(long)lrow * D_DIM + d0 + lcol];
        float4 u1 = *(const float4*)&uh_b[(long)lrow * D_DIM + d0 + lcol + 4];

        wq_s[lcol + 0][lrow] = w0.x;
        wq_s[lcol + 1][lrow] = w0.y;
        wq_s[lcol + 2][lrow] = w0.z;
        wq_s[lcol + 3][lrow] = w0.w;
        wq_s[lcol + 4][lrow] = w1.x;
        wq_s[lcol + 5][lrow] = w1.y;
        wq_s[lcol + 6][lrow] = w1.z;
        wq_s[lcol + 7][lrow] = w1.w;
        uh_s[lcol + 0][lrow] = u0.x;
        uh_s[lcol + 1][lrow] = u0.y;
        uh_s[lcol + 2][lrow] = u0.z;
        uh_s[lcol + 3][lrow] = u0.w;
        uh_s[lcol + 4][lrow] = u1.x;
        uh_s[lcol + 5][lrow] = u1.y;
        uh_s[lcol + 6][lrow] = u1.z;
        uh_s[lcol + 7][lrow] = u1.w;
        if (tid < 16) *(float4*)&v_s[tid * 4] = *(const float4*)&v[d0 + tid * 4];
        __syncthreads();

        #pragma unroll 16
        for (int d = 0; d < 64; d++) {
            float2 a = *(const float2*)&wq_s[d][tt * 2];
            float2 u = *(const float2*)&uh_s[d][ss * 2];
            float vd = v_s[d];
            acc00 = fmaf(vd, tanh_fast(a.x + u.x), acc00);
            acc01 = fmaf(vd, tanh_fast(a.x + u.y), acc01);
            acc10 = fmaf(vd, tanh_fast(a.y + u.x), acc10);
            acc11 = fmaf(vd, tanh_fast(a.y + u.y), acc11);
        }
        __syncthreads();
    }

    long base = ((long)b * T_DIM + t0 + tt * 2) * S_DIM + s0 + ss * 2;
    score[base]             = acc00;
    score[base + 1]         = acc01;
    score[base + S_DIM]     = acc10;
    score[base + S_DIM + 1] = acc11;
}

// ---------------- masked softmax: warp per row (exact reference semantics) --------
__global__ __launch_bounds__(256) void softmax_kernel(
    const float* __restrict__ score, const int* __restrict__ mask,
    float* __restrict__ attn, float* __restrict__ attn_out)
{
    const int lane = threadIdx.x & 31;
    const int w    = threadIdx.x >> 5;
    const int row  = blockIdx.x * 8 + w;    // b*T + t
    const int b    = row >> 8;              // T = 256

    const float4* sr = (const float4*)(score + (long)row * S_DIM);
    float4 x0 = sr[lane];
    float4 x1 = sr[lane + 32];

    float m = fmaxf(fmaxf(fmaxf(x0.x, x0.y), fmaxf(x0.z, x0.w)),
                    fmaxf(fmaxf(x1.x, x1.y), fmaxf(x1.z, x1.w)));
    #pragma unroll
    for (int o = 16; o > 0; o >>= 1) m = fmaxf(m, __shfl_xor_sync(0xffffffffu, m, o));

    const int4* mp = (const int4*)(mask + b * S_DIM);
    int4 k0 = mp[lane];
    int4 k1 = mp[lane + 32];

    float4 e0, e1;
    e0.x = __expf(x0.x - m) * (1.0f - (float)k0.x);
    e0.y = __expf(x0.y - m) * (1.0f - (float)k0.y);
    e0.z = __expf(x0.z - m) * (1.0f - (float)k0.z);
    e0.w = __expf(x0.w - m) * (1.0f - (float)k0.w);
    e1.x = __expf(x1.x - m) * (1.0f - (float)k1.x);
    e1.y = __expf(x1.y - m) * (1.0f - (float)k1.y);
    e1.z = __expf(x1.z - m) * (1.0f - (float)k1.z);
    e1.w = __expf(x1.w - m) * (1.0f - (float)k1.w);

    float sum = e0.x + e0.y + e0.z + e0.w + e1.x + e1.y + e1.z + e1.w;
    #pragma unroll
    for (int o = 16; o > 0; o >>= 1) sum += __shfl_xor_sync(0xffffffffu, sum, o);

    float inv = 1.0f / sum;
    e0.x *= inv; e0.y *= inv; e0.z *= inv; e0.w *= inv;
    e1.x *= inv; e1.y *= inv; e1.z *= inv; e1.w *= inv;

    float4* ar = (float4*)(attn + (long)row * S_DIM);
    ar[lane]      = e0;
    ar[lane + 32] = e1;
    if (attn_out) {
        float4* ao = (float4*)(attn_out + (long)row * S_DIM);
        ao[lane]      = e0;
        ao[lane + 32] = e1;
    }
}

// ---------------- launch ----------------
extern "C" void kernel_launch(void* const* d_in, const int* in_sizes, int n_in,
                              void* d_out, int out_size)
{
    const float* output  = (const float*)d_in[0];
    const float* context = (const float*)d_in[1];
    const int*   mask    = (const int*)d_in[2];
    const float* Wq      = (const float*)d_in[3];
    const float* bq      = (const float*)d_in[4];
    const float* Wc      = (const float*)d_in[5];
    const float* v       = (const float*)d_in[6];
    const float* Wout    = (const float*)d_in[7];
    const float* bout    = (const float*)d_in[8];

    float *wq, *uh, *score, *attn, *mix;
    cudaGetSymbolAddress((void**)&wq,    g_wq);
    cudaGetSymbolAddress((void**)&uh,    g_uh);
    cudaGetSymbolAddress((void**)&score, g_score);
    cudaGetSymbolAddress((void**)&attn,  g_attn);
    cudaGetSymbolAddress((void**)&mix,   g_mix);

    float* out = (float*)d_out;
    const int out_elems  = B_DIM * T_DIM * D_DIM;   // 524288
    const int attn_elems = B_DIM * T_DIM * S_DIM;   // 262144
    float* attn_out = (out_size >= out_elems + attn_elems) ? (out + out_elems) : nullptr;

    // wq = output @ Wq + bq            (1024x512, K=512)
    gemm_tile<<<dim3(8, 16, 1), 128>>>(output, nullptr, Wq, wq, 512, 512, 512, bq, 0, 0, 0);
    // uh = context @ Wc                (1024x512, K=512)
    gemm_tile<<<dim3(8, 16, 1), 128>>>(context, nullptr, Wc, uh, 512, 512, 512, nullptr, 0, 0, 0);
    // score
    score_kernel<<<dim3(8, 8, 4), 256>>>(wq, uh, v, score);
    // masked softmax -> attn (+ copy to d_out tail)
    softmax_kernel<<<128, 256>>>(score, mask, attn, attn_out);
    // mix = attn @ context             (batched 256x512, K=256)
    gemm_tile<<<dim3(8, 4, 4), 128>>>(attn, nullptr, context, mix, 512, 256, 256, nullptr,
                                      (long)T_DIM * S_DIM, (long)S_DIM * D_DIM, (long)T_DIM * D_DIM);
    // out = [mix | output] @ Wout + bout   (1024x512, K=1024, fused concat)
    gemm_tile<<<dim3(8, 16, 1), 128>>>(mix, output, Wout, out, 512, 512, 1024, bout, 0, 0, 0);
}

// round 5
// speedup vs baseline: 1.8238x; 1.1609x over previous
#include <cuda_runtime.h>
#include <cuda_bf16.h>
#include <cstdint>

#define B_DIM 4
#define T_DIM 256
#define S_DIM 256
#define D_DIM 512

// ---------------- fp32 scratch ----------------
__device__ float g_wq[B_DIM * T_DIM * D_DIM];     // 2 MB
__device__ float g_uh[B_DIM * S_DIM * D_DIM];     // 2 MB
__device__ float g_score[B_DIM * T_DIM * S_DIM];  // 1 MB
__device__ float g_mix[B_DIM * T_DIM * D_DIM];    // 2 MB

// ---------------- bf16 split scratch ----------------
__device__ __nv_bfloat16 g_out_hi[524288],  g_out_lo[524288];    // output [1024,512]
__device__ __nv_bfloat16 g_ctx_hi[524288],  g_ctx_lo[524288];    // context [1024,512]
__device__ __nv_bfloat16 g_ctxT_hi[524288], g_ctxT_lo[524288];   // context^T per batch [4][512][256]
__device__ __nv_bfloat16 g_WqT_hi[262144],  g_WqT_lo[262144];    // Wq^T [512,512]
__device__ __nv_bfloat16 g_WcT_hi[262144],  g_WcT_lo[262144];    // Wc^T [512,512]
__device__ __nv_bfloat16 g_WoT_hi[524288],  g_WoT_lo[524288];    // Wout^T [512,1024]
__device__ __nv_bfloat16 g_at_hi[262144],   g_at_lo[262144];     // attn [1024,256]
__device__ __nv_bfloat16 g_mx_hi[524288],   g_mx_lo[524288];     // mix [1024,512]

__device__ __forceinline__ float tanh_fast(float x) {
    float y;
    asm("tanh.approx.f32 %0, %1;" : "=f"(y) : "f"(x));
    return y;
}

// ---------------- elementwise split: hi = bf16(x), lo = bf16(x - hi) ----------------
__global__ __launch_bounds__(256) void split_kernel(
    const float* __restrict__ src,
    __nv_bfloat16* __restrict__ hi, __nv_bfloat16* __restrict__ lo, int n)
{
    for (int i = (blockIdx.x * 256 + threadIdx.x) * 4; i < n; i += gridDim.x * 1024) {
        float4 x = *(const float4*)(src + i);
        __nv_bfloat16 h0 = __float2bfloat16(x.x);
        __nv_bfloat16 h1 = __float2bfloat16(x.y);
        __nv_bfloat16 h2 = __float2bfloat16(x.z);
        __nv_bfloat16 h3 = __float2bfloat16(x.w);
        __nv_bfloat162 hh0; hh0.x = h0; hh0.y = h1;
        __nv_bfloat162 hh1; hh1.x = h2; hh1.y = h3;
        __nv_bfloat162 ll0;
        ll0.x = __float2bfloat16(x.x - __bfloat162float(h0));
        ll0.y = __float2bfloat16(x.y - __bfloat162float(h1));
        __nv_bfloat162 ll1;
        ll1.x = __float2bfloat16(x.z - __bfloat162float(h2));
        ll1.y = __float2bfloat16(x.w - __bfloat162float(h3));
        *(__nv_bfloat162*)(hi + i)     = hh0;
        *(__nv_bfloat162*)(hi + i + 2) = hh1;
        *(__nv_bfloat162*)(lo + i)     = ll0;
        *(__nv_bfloat162*)(lo + i + 2) = ll1;
    }
}

// ---------------- split + transpose: out[c][r] = split(src[r][c]) ----------------
__global__ __launch_bounds__(256) void splitT_kernel(
    const float* __restrict__ src,
    __nv_bfloat16* __restrict__ hiT, __nv_bfloat16* __restrict__ loT,
    int R, int C, long sSrc, long sOut)
{
    src += (long)blockIdx.z * sSrc;
    hiT += (long)blockIdx.z * sOut;
    loT += (long)blockIdx.z * sOut;

    __shared__ float tile[32][33];
    const int r0 = blockIdx.y * 32, c0 = blockIdx.x * 32;
    const int tx = threadIdx.x, ty = threadIdx.y;   // 32 x 8

    #pragma unroll
    for (int i = 0; i < 4; i++)
        tile[ty + i * 8][tx] = src[(long)(r0 + ty + i * 8) * C + c0 + tx];
    __syncthreads();
    #pragma unroll
    for (int i = 0; i < 4; i++) {
        int cr = c0 + ty + i * 8;
        float x = tile[tx][ty + i * 8];
        __nv_bfloat16 h = __float2bfloat16(x);
        hiT[(long)cr * R + r0 + tx] = h;
        loT[(long)cr * R + r0 + tx] = __float2bfloat16(x - __bfloat162float(h));
    }
}

// ---------------- split-bf16 tensor-core GEMM ----------------
// C[M,N] = [A|A2][M,Ktot] @ B[Ktot,N] (+bias), with all operands pre-split
// into bf16 hi/lo and B stored TRANSPOSED: B*[n][k]. 3 mma per product:
// hi*hi + hi*lo + lo*hi. Block tile 64x64, 4 warps (2x2), warp tile 32x32.
#define MMA_BF16(d, a, b)                                                     \
    asm volatile("mma.sync.aligned.m16n8k16.row.col.f32.bf16.bf16.f32 "       \
                 "{%0,%1,%2,%3},{%4,%5,%6,%7},{%8,%9},{%0,%1,%2,%3};"         \
                 : "+f"((d)[0]), "+f"((d)[1]), "+f"((d)[2]), "+f"((d)[3])     \
                 : "r"((a)[0]), "r"((a)[1]), "r"((a)[2]), "r"((a)[3]),        \
                   "r"((b)[0]), "r"((b)[1]))

__global__ __launch_bounds__(128) void gemm_bf16s(
    const __nv_bfloat16* __restrict__ Ahi, const __nv_bfloat16* __restrict__ Alo,
    const __nv_bfloat16* __restrict__ A2hi, const __nv_bfloat16* __restrict__ A2lo,
    const __nv_bfloat16* __restrict__ BThi, const __nv_bfloat16* __restrict__ BTlo,
    float* __restrict__ C, int N, int Ka, int Ktot,
    const float* __restrict__ bias, long sA, long sB, long sC)
{
    Ahi  += (long)blockIdx.z * sA;  Alo  += (long)blockIdx.z * sA;
    BThi += (long)blockIdx.z * sB;  BTlo += (long)blockIdx.z * sB;
    C    += (long)blockIdx.z * sC;

    // 64 rows x 16 k, padded row stride 24 bf16 (48B -> conflict-free frags)
    __shared__ __align__(16) __nv_bfloat16 As[2][2][64 * 24];
    __shared__ __align__(16) __nv_bfloat16 Bs[2][2][64 * 24];

    const int tid  = threadIdx.x;
    const int lane = tid & 31;
    const int wid  = tid >> 5;
    const int wm   = wid >> 1, wn = wid & 1;
    const int m0   = blockIdx.y * 64;
    const int n0   = blockIdx.x * 64;
    const int row  = tid >> 1;       // 0..63 staging row
    const int seg  = tid & 1;        // 0/1 -> 8 bf16 segment
    const int g    = lane >> 2;      // 0..7
    const int t    = lane & 3;       // 0..3

    const int Kb = Ktot - Ka;
    const int KT = Ktot >> 4;

    int4 ra_h, ra_l, rb_h, rb_l;

#define LDG(kt) {                                                              \
        int gk = (kt) << 4;                                                    \
        const __nv_bfloat16 *aph, *apl;                                        \
        if (A2hi && gk >= Ka) {                                                \
            long off = (long)(m0 + row) * Kb + (gk - Ka) + seg * 8;            \
            aph = A2hi + off; apl = A2lo + off;                                \
        } else {                                                               \
            long off = (long)(m0 + row) * Ka + gk + seg * 8;                   \
            aph = Ahi + off; apl = Alo + off;                                  \
        }                                                                      \
        ra_h = *(const int4*)aph;                                              \
        ra_l = *(const int4*)apl;                                              \
        long boff = (long)(n0 + row) * Ktot + gk + seg * 8;                    \
        rb_h = *(const int4*)(BThi + boff);                                    \
        rb_l = *(const int4*)(BTlo + boff);                                    \
    }

#define STS(bf) {                                                              \
        int so = row * 24 + seg * 8;                                           \
        *(int4*)&As[bf][0][so] = ra_h;                                         \
        *(int4*)&As[bf][1][so] = ra_l;                                         \
        *(int4*)&Bs[bf][0][so] = rb_h;                                         \
        *(int4*)&Bs[bf][1][so] = rb_l;                                         \
    }

    float acc[2][4][4] = {};

    LDG(0); STS(0);
    __syncthreads();

    for (int kt = 0; kt < KT; kt++) {
        const int buf = kt & 1;
        if (kt + 1 < KT) LDG(kt + 1);

        uint32_t ah[2][4], al[2][4], bh[4][2], bl[4][2];
        const __nv_bfloat16* pah = &As[buf][0][0];
        const __nv_bfloat16* pal = &As[buf][1][0];
        const __nv_bfloat16* pbh = &Bs[buf][0][0];
        const __nv_bfloat16* pbl = &Bs[buf][1][0];

        #pragma unroll
        for (int mi = 0; mi < 2; mi++) {
            int base = (wm * 32 + mi * 16 + g) * 24 + 2 * t;
            ah[mi][0] = *(const uint32_t*)(pah + base);
            ah[mi][1] = *(const uint32_t*)(pah + base + 8 * 24);
            ah[mi][2] = *(const uint32_t*)(pah + base + 8);
            ah[mi][3] = *(const uint32_t*)(pah + base + 8 * 24 + 8);
            al[mi][0] = *(const uint32_t*)(pal + base);
            al[mi][1] = *(const uint32_t*)(pal + base + 8 * 24);
            al[mi][2] = *(const uint32_t*)(pal + base + 8);
            al[mi][3] = *(const uint32_t*)(pal + base + 8 * 24 + 8);
        }
        #pragma unroll
        for (int nj = 0; nj < 4; nj++) {
            int base = (wn * 32 + nj * 8 + g) * 24 + 2 * t;
            bh[nj][0] = *(const uint32_t*)(pbh + base);
            bh[nj][1] = *(const uint32_t*)(pbh + base + 8);
            bl[nj][0] = *(const uint32_t*)(pbl + base);
            bl[nj][1] = *(const uint32_t*)(pbl + base + 8);
        }

        #pragma unroll
        for (int mi = 0; mi < 2; mi++)
            #pragma unroll
            for (int nj = 0; nj < 4; nj++) {
                MMA_BF16(acc[mi][nj], ah[mi], bh[nj]);
                MMA_BF16(acc[mi][nj], ah[mi], bl[nj]);
                MMA_BF16(acc[mi][nj], al[mi], bh[nj]);
            }

        if (kt + 1 < KT) STS(buf ^ 1);
        __syncthreads();
    }

    #pragma unroll
    for (int mi = 0; mi < 2; mi++)
        #pragma unroll
        for (int nj = 0; nj < 4; nj++) {
            int r = m0 + wm * 32 + mi * 16 + g;
            int c = n0 + wn * 32 + nj * 8 + 2 * t;
            float b0 = 0.f, b1 = 0.f;
            if (bias) { b0 = bias[c]; b1 = bias[c + 1]; }
            float2 o0, o1;
            o0.x = acc[mi][nj][0] + b0; o0.y = acc[mi][nj][1] + b1;
            o1.x = acc[mi][nj][2] + b0; o1.y = acc[mi][nj][3] + b1;
            *(float2*)&C[(long)r * N + c]       = o0;
            *(float2*)&C[(long)(r + 8) * N + c] = o1;
        }
#undef LDG
#undef STS
}

// ---------------- score kernel (unchanged from r4) ----------------
__global__ __launch_bounds__(256) void score_kernel(
    const float* __restrict__ wq, const float* __restrict__ uh,
    const float* __restrict__ v, float* __restrict__ score)
{
    const int b  = blockIdx.z;
    const int t0 = blockIdx.y * 32;
    const int s0 = blockIdx.x * 32;

    __shared__ float wq_s[64][34];
    __shared__ float uh_s[64][34];
    __shared__ float v_s[64];

    const int tid  = threadIdx.x;
    const int tt   = tid >> 4;
    const int ss   = tid & 15;
    const int lrow = tid >> 3;
    const int lcol = (tid & 7) * 8;

    const float* wq_b = wq + ((long)b * T_DIM + t0) * D_DIM;
    const float* uh_b = uh + ((long)b * S_DIM + s0) * D_DIM;

    float acc00 = 0.f, acc01 = 0.f, acc10 = 0.f, acc11 = 0.f;

    for (int d0 = 0; d0 < D_DIM; d0 += 64) {
        float4 w0 = *(const float4*)&wq_b[(long)lrow * D_DIM + d0 + lcol];
        float4 w1 = *(const float4*)&wq_b[(long)lrow * D_DIM + d0 + lcol + 4];
        float4 u0 = *(const float4*)&uh_b[(long)lrow * D_DIM + d0 + lcol];
        float4 u1 = *(const float4*)&uh_b[(long)lrow * D_DIM + d0 + lcol + 4];

        wq_s[lcol + 0][lrow] = w0.x; wq_s[lcol + 1][lrow] = w0.y;
        wq_s[lcol + 2][lrow] = w0.z; wq_s[lcol + 3][lrow] = w0.w;
        wq_s[lcol + 4][lrow] = w1.x; wq_s[lcol + 5][lrow] = w1.y;
        wq_s[lcol + 6][lrow] = w1.z; wq_s[lcol + 7][lrow] = w1.w;
        uh_s[lcol + 0][lrow] = u0.x; uh_s[lcol + 1][lrow] = u0.y;
        uh_s[lcol + 2][lrow] = u0.z; uh_s[lcol + 3][lrow] = u0.w;
        uh_s[lcol + 4][lrow] = u1.x; uh_s[lcol + 5][lrow] = u1.y;
        uh_s[lcol + 6][lrow] = u1.z; uh_s[lcol + 7][lrow] = u1.w;
        if (tid < 16) *(float4*)&v_s[tid * 4] = *(const float4*)&v[d0 + tid * 4];
        __syncthreads();

        #pragma unroll 16
        for (int d = 0; d < 64; d++) {
            float2 a = *(const float2*)&wq_s[d][tt * 2];
            float2 u = *(const float2*)&uh_s[d][ss * 2];
            float vd = v_s[d];
            acc00 = fmaf(vd, tanh_fast(a.x + u.x), acc00);
            acc01 = fmaf(vd, tanh_fast(a.x + u.y), acc01);
            acc10 = fmaf(vd, tanh_fast(a.y + u.x), acc10);
            acc11 = fmaf(vd, tanh_fast(a.y + u.y), acc11);
        }
        __syncthreads();
    }

    long base = ((long)b * T_DIM + t0 + tt * 2) * S_DIM + s0 + ss * 2;
    score[base]             = acc00;
    score[base + 1]         = acc01;
    score[base + S_DIM]     = acc10;
    score[base + S_DIM + 1] = acc11;
}

// ---------------- masked softmax + fused attn hi/lo split ----------------
__device__ __forceinline__ void wr_split2(
    __nv_bfloat16* hp, __nv_bfloat16* lp, int c, float a, float b)
{
    __nv_bfloat16 h0 = __float2bfloat16(a);
    __nv_bfloat16 h1 = __float2bfloat16(b);
    __nv_bfloat162 hh; hh.x = h0; hh.y = h1;
    __nv_bfloat162 ll;
    ll.x = __float2bfloat16(a - __bfloat162float(h0));
    ll.y = __float2bfloat16(b - __bfloat162float(h1));
    *(__nv_bfloat162*)(hp + c) = hh;
    *(__nv_bfloat162*)(lp + c) = ll;
}

__global__ __launch_bounds__(256) void softmax_kernel(
    const float* __restrict__ score, const int* __restrict__ mask,
    __nv_bfloat16* __restrict__ at_hi, __nv_bfloat16* __restrict__ at_lo,
    float* __restrict__ attn_out)
{
    const int lane = threadIdx.x & 31;
    const int w    = threadIdx.x >> 5;
    const int row  = blockIdx.x * 8 + w;    // b*T + t
    const int b    = row >> 8;              // T = 256

    const float4* sr = (const float4*)(score + (long)row * S_DIM);
    float4 x0 = sr[lane];
    float4 x1 = sr[lane + 32];

    float m = fmaxf(fmaxf(fmaxf(x0.x, x0.y), fmaxf(x0.z, x0.w)),
                    fmaxf(fmaxf(x1.x, x1.y), fmaxf(x1.z, x1.w)));
    #pragma unroll
    for (int o = 16; o > 0; o >>= 1) m = fmaxf(m, __shfl_xor_sync(0xffffffffu, m, o));

    const int4* mp = (const int4*)(mask + b * S_DIM);
    int4 k0 = mp[lane];
    int4 k1 = mp[lane + 32];

    float4 e0, e1;
    e0.x = __expf(x0.x - m) * (1.0f - (float)k0.x);
    e0.y = __expf(x0.y - m) * (1.0f - (float)k0.y);
    e0.z = __expf(x0.z - m) * (1.0f - (float)k0.z);
    e0.w = __expf(x0.w - m) * (1.0f - (float)k0.w);
    e1.x = __expf(x1.x - m) * (1.0f - (float)k1.x);
    e1.y = __expf(x1.y - m) * (1.0f - (float)k1.y);
    e1.z = __expf(x1.z - m) * (1.0f - (float)k1.z);
    e1.w = __expf(x1.w - m) * (1.0f - (float)k1.w);

    float sum = e0.x + e0.y + e0.z + e0.w + e1.x + e1.y + e1.z + e1.w;
    #pragma unroll
    for (int o = 16; o > 0; o >>= 1) sum += __shfl_xor_sync(0xffffffffu, sum, o);

    float inv = 1.0f / sum;
    e0.x *= inv; e0.y *= inv; e0.z *= inv; e0.w *= inv;
    e1.x *= inv; e1.y *= inv; e1.z *= inv; e1.w *= inv;

    __nv_bfloat16* hp = at_hi + (long)row * S_DIM;
    __nv_bfloat16* lp = at_lo + (long)row * S_DIM;
    wr_split2(hp, lp, 4 * lane,       e0.x, e0.y);
    wr_split2(hp, lp, 4 * lane + 2,   e0.z, e0.w);
    wr_split2(hp, lp, 128 + 4 * lane, e1.x, e1.y);
    wr_split2(hp, lp, 130 + 4 * lane, e1.z, e1.w);

    if (attn_out) {
        float4* ao = (float4*)(attn_out + (long)row * S_DIM);
        ao[lane]      = e0;
        ao[lane + 32] = e1;
    }
}

// ---------------- launch ----------------
extern "C" void kernel_launch(void* const* d_in, const int* in_sizes, int n_in,
                              void* d_out, int out_size)
{
    const float* output  = (const float*)d_in[0];
    const float* context = (const float*)d_in[1];
    const int*   mask    = (const int*)d_in[2];
    const float* Wq      = (const float*)d_in[3];
    const float* bq      = (const float*)d_in[4];
    const float* Wc      = (const float*)d_in[5];
    const float* v       = (const float*)d_in[6];
    const float* Wout    = (const float*)d_in[7];
    const float* bout    = (const float*)d_in[8];

    float *wq, *uh, *score, *mix;
    cudaGetSymbolAddress((void**)&wq,    g_wq);
    cudaGetSymbolAddress((void**)&uh,    g_uh);
    cudaGetSymbolAddress((void**)&score, g_score);
    cudaGetSymbolAddress((void**)&mix,   g_mix);

    __nv_bfloat16 *out_hi, *out_lo, *ctx_hi, *ctx_lo, *ctxT_hi, *ctxT_lo;
    __nv_bfloat16 *WqT_hi, *WqT_lo, *WcT_hi, *WcT_lo, *WoT_hi, *WoT_lo;
    __nv_bfloat16 *at_hi, *at_lo, *mx_hi, *mx_lo;
    cudaGetSymbolAddress((void**)&out_hi,  g_out_hi);
    cudaGetSymbolAddress((void**)&out_lo,  g_out_lo);
    cudaGetSymbolAddress((void**)&ctx_hi,  g_ctx_hi);
    cudaGetSymbolAddress((void**)&ctx_lo,  g_ctx_lo);
    cudaGetSymbolAddress((void**)&ctxT_hi, g_ctxT_hi);
    cudaGetSymbolAddress((void**)&ctxT_lo, g_ctxT_lo);
    cudaGetSymbolAddress((void**)&WqT_hi,  g_WqT_hi);
    cudaGetSymbolAddress((void**)&WqT_lo,  g_WqT_lo);
    cudaGetSymbolAddress((void**)&WcT_hi,  g_WcT_hi);
    cudaGetSymbolAddress((void**)&WcT_lo,  g_WcT_lo);
    cudaGetSymbolAddress((void**)&WoT_hi,  g_WoT_hi);
    cudaGetSymbolAddress((void**)&WoT_lo,  g_WoT_lo);
    cudaGetSymbolAddress((void**)&at_hi,   g_at_hi);
    cudaGetSymbolAddress((void**)&at_lo,   g_at_lo);
    cudaGetSymbolAddress((void**)&mx_hi,   g_mx_hi);
    cudaGetSymbolAddress((void**)&mx_lo,   g_mx_lo);

    float* out = (float*)d_out;
    const int out_elems  = B_DIM * T_DIM * D_DIM;   // 524288
    const int attn_elems = B_DIM * T_DIM * S_DIM;   // 262144
    float* attn_out = (out_size >= out_elems + attn_elems) ? (out + out_elems) : nullptr;

    const dim3 tb(32, 8);

    // Stage: splits + transposes (independent)
    split_kernel<<<256, 256>>>(output,  out_hi, out_lo, 524288);
    split_kernel<<<256, 256>>>(context, ctx_hi, ctx_lo, 524288);
    splitT_kernel<<<dim3(16, 16, 1), tb>>>(Wq,   WqT_hi, WqT_lo, 512, 512, 0, 0);
    splitT_kernel<<<dim3(16, 16, 1), tb>>>(Wc,   WcT_hi, WcT_lo, 512, 512, 0, 0);
    splitT_kernel<<<dim3(16, 32, 1), tb>>>(Wout, WoT_hi, WoT_lo, 1024, 512, 0, 0);
    splitT_kernel<<<dim3(16, 8, 4),  tb>>>(context, ctxT_hi, ctxT_lo, 256, 512,
                                           (long)S_DIM * D_DIM, (long)S_DIM * D_DIM);

    // wq = output @ Wq + bq   (M=1024, N=512, K=512)
    gemm_bf16s<<<dim3(8, 16, 1), 128>>>(out_hi, out_lo, nullptr, nullptr,
                                        WqT_hi, WqT_lo, wq, 512, 512, 512, bq, 0, 0, 0);
    // uh = context @ Wc
    gemm_bf16s<<<dim3(8, 16, 1), 128>>>(ctx_hi, ctx_lo, nullptr, nullptr,
                                        WcT_hi, WcT_lo, uh, 512, 512, 512, nullptr, 0, 0, 0);
    // score
    score_kernel<<<dim3(8, 8, 4), 256>>>(wq, uh, v, score);
    // softmax (+ attn split, + d_out tail)
    softmax_kernel<<<128, 256>>>(score, mask, at_hi, at_lo, attn_out);
    // mix = attn @ context  (batched, M=256, N=512, K=256)
    gemm_bf16s<<<dim3(8, 4, 4), 128>>>(at_hi, at_lo, nullptr, nullptr,
                                       ctxT_hi, ctxT_lo, mix, 512, 256, 256, nullptr,
                                       (long)T_DIM * S_DIM, (long)S_DIM * D_DIM,
                                       (long)T_DIM * D_DIM);
    // split mix
    split_kernel<<<256, 256>>>(mix, mx_hi, mx_lo, 524288);
    // out = [mix | output] @ Wout + bout  (M=1024, N=512, Ktot=1024)
    gemm_bf16s<<<dim3(8, 16, 1), 128>>>(mx_hi, mx_lo, out_hi, out_lo,
                                        WoT_hi, WoT_lo, out, 512, 512, 1024, bout, 0, 0, 0);
}

// round 6
// speedup vs baseline: 1.9601x; 1.0747x over previous
#include <cuda_runtime.h>
#include <cuda_bf16.h>
#include <cstdint>

#define B_DIM 4
#define T_DIM 256
#define S_DIM 256
#define D_DIM 512

// ---------------- fp32 scratch ----------------
__device__ float g_wq[B_DIM * T_DIM * D_DIM];     // 2 MB
__device__ float g_uh[B_DIM * S_DIM * D_DIM];     // 2 MB
__device__ float g_score[B_DIM * T_DIM * S_DIM];  // 1 MB

// ---------------- bf16 split scratch ----------------
__device__ __nv_bfloat16 g_out_hi[524288],  g_out_lo[524288];    // output [1024,512]
__device__ __nv_bfloat16 g_ctx_hi[524288],  g_ctx_lo[524288];    // context [1024,512]
__device__ __nv_bfloat16 g_ctxT_hi[524288], g_ctxT_lo[524288];   // context^T [4][512][256]
__device__ __nv_bfloat16 g_WqT_hi[262144],  g_WqT_lo[262144];    // Wq^T [512,512]
__device__ __nv_bfloat16 g_WcT_hi[262144],  g_WcT_lo[262144];    // Wc^T [512,512]
__device__ __nv_bfloat16 g_WoT_hi[524288],  g_WoT_lo[524288];    // Wout^T [512,1024]
__device__ __nv_bfloat16 g_at_hi[262144],   g_at_lo[262144];     // attn [1024,256]
__device__ __nv_bfloat16 g_mx_hi[524288],   g_mx_lo[524288];     // mix [1024,512]

// ---------------- streams/events for graph fork-join (created before main) ----------
static cudaStream_t s1, s2, s3;
static cudaEvent_t  evFork, ev1, ev2, ev3;
struct StreamInit {
    StreamInit() {
        cudaStreamCreateWithFlags(&s1, cudaStreamNonBlocking);
        cudaStreamCreateWithFlags(&s2, cudaStreamNonBlocking);
        cudaStreamCreateWithFlags(&s3, cudaStreamNonBlocking);
        cudaEventCreateWithFlags(&evFork, cudaEventDisableTiming);
        cudaEventCreateWithFlags(&ev1, cudaEventDisableTiming);
        cudaEventCreateWithFlags(&ev2, cudaEventDisableTiming);
        cudaEventCreateWithFlags(&ev3, cudaEventDisableTiming);
    }
};
static StreamInit g_streams_init;

__device__ __forceinline__ float tanh_fast(float x) {
    float y;
    asm("tanh.approx.f32 %0, %1;" : "=f"(y) : "f"(x));
    return y;
}

// ---------------- elementwise split: hi = bf16(x), lo = bf16(x - hi) ----------------
__global__ __launch_bounds__(256) void split_kernel(
    const float* __restrict__ src,
    __nv_bfloat16* __restrict__ hi, __nv_bfloat16* __restrict__ lo, int n)
{
    for (int i = (blockIdx.x * 256 + threadIdx.x) * 4; i < n; i += gridDim.x * 1024) {
        float4 x = *(const float4*)(src + i);
        __nv_bfloat16 h0 = __float2bfloat16(x.x);
        __nv_bfloat16 h1 = __float2bfloat16(x.y);
        __nv_bfloat16 h2 = __float2bfloat16(x.z);
        __nv_bfloat16 h3 = __float2bfloat16(x.w);
        __nv_bfloat162 hh0; hh0.x = h0; hh0.y = h1;
        __nv_bfloat162 hh1; hh1.x = h2; hh1.y = h3;
        __nv_bfloat162 ll0;
        ll0.x = __float2bfloat16(x.x - __bfloat162float(h0));
        ll0.y = __float2bfloat16(x.y - __bfloat162float(h1));
        __nv_bfloat162 ll1;
        ll1.x = __float2bfloat16(x.z - __bfloat162float(h2));
        ll1.y = __float2bfloat16(x.w - __bfloat162float(h3));
        *(__nv_bfloat162*)(hi + i)     = hh0;
        *(__nv_bfloat162*)(hi + i + 2) = hh1;
        *(__nv_bfloat162*)(lo + i)     = ll0;
        *(__nv_bfloat162*)(lo + i + 2) = ll1;
    }
}

// ---------------- split + transpose: out[c][r] = split(src[r][c]) ----------------
__global__ __launch_bounds__(256) void splitT_kernel(
    const float* __restrict__ src,
    __nv_bfloat16* __restrict__ hiT, __nv_bfloat16* __restrict__ loT,
    int R, int C, long sSrc, long sOut)
{
    src += (long)blockIdx.z * sSrc;
    hiT += (long)blockIdx.z * sOut;
    loT += (long)blockIdx.z * sOut;

    __shared__ float tile[32][33];
    const int r0 = blockIdx.y * 32, c0 = blockIdx.x * 32;
    const int tx = threadIdx.x, ty = threadIdx.y;   // 32 x 8

    #pragma unroll
    for (int i = 0; i < 4; i++)
        tile[ty + i * 8][tx] = src[(long)(r0 + ty + i * 8) * C + c0 + tx];
    __syncthreads();
    #pragma unroll
    for (int i = 0; i < 4; i++) {
        int cr = c0 + ty + i * 8;
        float x = tile[tx][ty + i * 8];
        __nv_bfloat16 h = __float2bfloat16(x);
        hiT[(long)cr * R + r0 + tx] = h;
        loT[(long)cr * R + r0 + tx] = __float2bfloat16(x - __bfloat162float(h));
    }
}

// ---------------- split-bf16 tensor-core GEMM (256 thr, 8 warps, 64x64 tile) ----
// C = [A|A2] @ B (+bias). B transposed [n][k]. hi*hi + hi*lo + lo*hi.
// Optional epilogue: write hi/lo bf16 split instead of fp32 C.
#define MMA_BF16(d, a, b)                                                     \
    asm volatile("mma.sync.aligned.m16n8k16.row.col.f32.bf16.bf16.f32 "       \
                 "{%0,%1,%2,%3},{%4,%5,%6,%7},{%8,%9},{%0,%1,%2,%3};"         \
                 : "+f"((d)[0]), "+f"((d)[1]), "+f"((d)[2]), "+f"((d)[3])     \
                 : "r"((a)[0]), "r"((a)[1]), "r"((a)[2]), "r"((a)[3]),        \
                   "r"((b)[0]), "r"((b)[1]))

__global__ __launch_bounds__(256) void gemm_bf16s(
    const __nv_bfloat16* __restrict__ Ahi, const __nv_bfloat16* __restrict__ Alo,
    const __nv_bfloat16* __restrict__ A2hi, const __nv_bfloat16* __restrict__ A2lo,
    const __nv_bfloat16* __restrict__ BThi, const __nv_bfloat16* __restrict__ BTlo,
    float* __restrict__ C,
    __nv_bfloat16* __restrict__ Chi, __nv_bfloat16* __restrict__ Clo,
    int N, int Ka, int Ktot, const float* __restrict__ bias,
    long sA, long sB, long sC)
{
    Ahi  += (long)blockIdx.z * sA;  Alo  += (long)blockIdx.z * sA;
    BThi += (long)blockIdx.z * sB;  BTlo += (long)blockIdx.z * sB;
    if (C)   C   += (long)blockIdx.z * sC;
    if (Chi) { Chi += (long)blockIdx.z * sC; Clo += (long)blockIdx.z * sC; }

    __shared__ __align__(16) __nv_bfloat16 As[2][2][64 * 24];  // [buf][hi/lo][row*24+k]
    __shared__ __align__(16) __nv_bfloat16 Bs[2][2][64 * 24];

    const int tid  = threadIdx.x;
    const int lane = tid & 31;
    const int wid  = tid >> 5;          // 0..7
    const int wm   = wid & 1;           // 2 -> rows
    const int wn   = wid >> 1;          // 4 -> cols
    const int m0   = blockIdx.y * 64;
    const int n0   = blockIdx.x * 64;
    const int g    = lane >> 2;         // 0..7
    const int t    = lane & 3;          // 0..3
    // staging: 256 threads, each one int4 for A-side and one for B-side
    const int arow = tid >> 2;          // 0..63
    const int part = (tid >> 1) & 1;    // hi / lo
    const int seg  = tid & 1;           // k-segment (8 bf16)

    const int Kb = Ktot - Ka;
    const int KT = Ktot >> 4;

    int4 ra, rb;

#define LDG(kt) {                                                              \
        int gk = (kt) << 4;                                                    \
        const __nv_bfloat16 *ap;                                               \
        if (A2hi && gk >= Ka) {                                                \
            long off = (long)(m0 + arow) * Kb + (gk - Ka) + seg * 8;           \
            ap = (part ? A2lo : A2hi) + off;                                   \
        } else {                                                               \
            long off = (long)(m0 + arow) * Ka + gk + seg * 8;                  \
            ap = (part ? Alo : Ahi) + off;                                     \
        }                                                                      \
        ra = *(const int4*)ap;                                                 \
        long boff = (long)(n0 + arow) * Ktot + gk + seg * 8;                   \
        rb = *(const int4*)((part ? BTlo : BThi) + boff);                      \
    }

#define STS(bf) {                                                              \
        int so = arow * 24 + seg * 8;                                          \
        *(int4*)&As[bf][part][so] = ra;                                        \
        *(int4*)&Bs[bf][part][so] = rb;                                        \
    }

    float acc[2][2][4] = {};

    LDG(0); STS(0);
    __syncthreads();

    for (int kt = 0; kt < KT; kt++) {
        const int buf = kt & 1;
        if (kt + 1 < KT) LDG(kt + 1);

        uint32_t ah[2][4], al[2][4], bh[2][2], bl[2][2];
        const __nv_bfloat16* pah = &As[buf][0][0];
        const __nv_bfloat16* pal = &As[buf][1][0];
        const __nv_bfloat16* pbh = &Bs[buf][0][0];
        const __nv_bfloat16* pbl = &Bs[buf][1][0];

        #pragma unroll
        for (int mi = 0; mi < 2; mi++) {
            int base = (wm * 32 + mi * 16 + g) * 24 + 2 * t;
            ah[mi][0] = *(const uint32_t*)(pah + base);
            ah[mi][1] = *(const uint32_t*)(pah + base + 8 * 24);
            ah[mi][2] = *(const uint32_t*)(pah + base + 8);
            ah[mi][3] = *(const uint32_t*)(pah + base + 8 * 24 + 8);
            al[mi][0] = *(const uint32_t*)(pal + base);
            al[mi][1] = *(const uint32_t*)(pal + base + 8 * 24);
            al[mi][2] = *(const uint32_t*)(pal + base + 8);
            al[mi][3] = *(const uint32_t*)(pal + base + 8 * 24 + 8);
        }
        #pragma unroll
        for (int nj = 0; nj < 2; nj++) {
            int base = (wn * 16 + nj * 8 + g) * 24 + 2 * t;
            bh[nj][0] = *(const uint32_t*)(pbh + base);
            bh[nj][1] = *(const uint32_t*)(pbh + base + 8);
            bl[nj][0] = *(const uint32_t*)(pbl + base);
            bl[nj][1] = *(const uint32_t*)(pbl + base + 8);
        }

        #pragma unroll
        for (int mi = 0; mi < 2; mi++)
            #pragma unroll
            for (int nj = 0; nj < 2; nj++) {
                MMA_BF16(acc[mi][nj], ah[mi], bh[nj]);
                MMA_BF16(acc[mi][nj], ah[mi], bl[nj]);
                MMA_BF16(acc[mi][nj], al[mi], bh[nj]);
            }

        if (kt + 1 < KT) STS(buf ^ 1);
        __syncthreads();
    }

    #pragma unroll
    for (int mi = 0; mi < 2; mi++)
        #pragma unroll
        for (int nj = 0; nj < 2; nj++) {
            int r = m0 + wm * 32 + mi * 16 + g;
            int c = n0 + wn * 16 + nj * 8 + 2 * t;
            float b0 = 0.f, b1 = 0.f;
            if (bias) { b0 = bias[c]; b1 = bias[c + 1]; }
            float v0 = acc[mi][nj][0] + b0, v1 = acc[mi][nj][1] + b1;
            float v2 = acc[mi][nj][2] + b0, v3 = acc[mi][nj][3] + b1;
            if (Chi) {
                __nv_bfloat162 hh0, ll0, hh1, ll1;
                hh0.x = __float2bfloat16(v0); hh0.y = __float2bfloat16(v1);
                ll0.x = __float2bfloat16(v0 - __bfloat162float(hh0.x));
                ll0.y = __float2bfloat16(v1 - __bfloat162float(hh0.y));
                hh1.x = __float2bfloat16(v2); hh1.y = __float2bfloat16(v3);
                ll1.x = __float2bfloat16(v2 - __bfloat162float(hh1.x));
                ll1.y = __float2bfloat16(v3 - __bfloat162float(hh1.y));
                *(__nv_bfloat162*)&Chi[(long)r * N + c]       = hh0;
                *(__nv_bfloat162*)&Clo[(long)r * N + c]       = ll0;
                *(__nv_bfloat162*)&Chi[(long)(r + 8) * N + c] = hh1;
                *(__nv_bfloat162*)&Clo[(long)(r + 8) * N + c] = ll1;
            } else {
                float2 o0; o0.x = v0; o0.y = v1;
                float2 o1; o1.x = v2; o1.y = v3;
                *(float2*)&C[(long)r * N + c]       = o0;
                *(float2*)&C[(long)(r + 8) * N + c] = o1;
            }
        }
#undef LDG
#undef STS
}

// ---------------- score kernel ----------------
__global__ __launch_bounds__(256) void score_kernel(
    const float* __restrict__ wq, const float* __restrict__ uh,
    const float* __restrict__ v, float* __restrict__ score)
{
    const int b  = blockIdx.z;
    const int t0 = blockIdx.y * 32;
    const int s0 = blockIdx.x * 32;

    __shared__ float wq_s[64][34];
    __shared__ float uh_s[64][34];
    __shared__ float v_s[64];

    const int tid  = threadIdx.x;
    const int tt   = tid >> 4;
    const int ss   = tid & 15;
    const int lrow = tid >> 3;
    const int lcol = (tid & 7) * 8;

    const float* wq_b = wq + ((long)b * T_DIM + t0) * D_DIM;
    const float* uh_b = uh + ((long)b * S_DIM + s0) * D_DIM;

    float acc00 = 0.f, acc01 = 0.f, acc10 = 0.f, acc11 = 0.f;

    for (int d0 = 0; d0 < D_DIM; d0 += 64) {
        float4 w0 = *(const float4*)&wq_b[(long)lrow * D_DIM + d0 + lcol];
        float4 w1 = *(const float4*)&wq_b[(long)lrow * D_DIM + d0 + lcol + 4];
        float4 u0 = *(const float4*)&uh_b[(long)lrow * D_DIM + d0 + lcol];
        float4 u1 = *(const float4*)&uh_b[(long)lrow * D_DIM + d0 + lcol + 4];

        wq_s[lcol + 0][lrow] = w0.x; wq_s[lcol + 1][lrow] = w0.y;
        wq_s[lcol + 2][lrow] = w0.z; wq_s[lcol + 3][lrow] = w0.w;
        wq_s[lcol + 4][lrow] = w1.x; wq_s[lcol + 5][lrow] = w1.y;
        wq_s[lcol + 6][lrow] = w1.z; wq_s[lcol + 7][lrow] = w1.w;
        uh_s[lcol + 0][lrow] = u0.x; uh_s[lcol + 1][lrow] = u0.y;
        uh_s[lcol + 2][lrow] = u0.z; uh_s[lcol + 3][lrow] = u0.w;
        uh_s[lcol + 4][lrow] = u1.x; uh_s[lcol + 5][lrow] = u1.y;
        uh_s[lcol + 6][lrow] = u1.z; uh_s[lcol + 7][lrow] = u1.w;
        if (tid < 16) *(float4*)&v_s[tid * 4] = *(const float4*)&v[d0 + tid * 4];
        __syncthreads();

        #pragma unroll 16
        for (int d = 0; d < 64; d++) {
            float2 a = *(const float2*)&wq_s[d][tt * 2];
            float2 u = *(const float2*)&uh_s[d][ss * 2];
            float vd = v_s[d];
            acc00 = fmaf(vd, tanh_fast(a.x + u.x), acc00);
            acc01 = fmaf(vd, tanh_fast(a.x + u.y), acc01);
            acc10 = fmaf(vd, tanh_fast(a.y + u.x), acc10);
            acc11 = fmaf(vd, tanh_fast(a.y + u.y), acc11);
        }
        __syncthreads();
    }

    long base = ((long)b * T_DIM + t0 + tt * 2) * S_DIM + s0 + ss * 2;
    score[base]             = acc00;
    score[base + 1]         = acc01;
    score[base + S_DIM]     = acc10;
    score[base + S_DIM + 1] = acc11;
}

// ---------------- masked softmax + fused attn hi/lo split ----------------
__device__ __forceinline__ void wr_split2(
    __nv_bfloat16* hp, __nv_bfloat16* lp, int c, float a, float b)
{
    __nv_bfloat16 h0 = __float2bfloat16(a);
    __nv_bfloat16 h1 = __float2bfloat16(b);
    __nv_bfloat162 hh; hh.x = h0; hh.y = h1;
    __nv_bfloat162 ll;
    ll.x = __float2bfloat16(a - __bfloat162float(h0));
    ll.y = __float2bfloat16(b - __bfloat162float(h1));
    *(__nv_bfloat162*)(hp + c) = hh;
    *(__nv_bfloat162*)(lp + c) = ll;
}

__global__ __launch_bounds__(256) void softmax_kernel(
    const float* __restrict__ score, const int* __restrict__ mask,
    __nv_bfloat16* __restrict__ at_hi, __nv_bfloat16* __restrict__ at_lo,
    float* __restrict__ attn_out)
{
    const int lane = threadIdx.x & 31;
    const int w    = threadIdx.x >> 5;
    const int row  = blockIdx.x * 8 + w;    // b*T + t
    const int b    = row >> 8;              // T = 256

    const float4* sr = (const float4*)(score + (long)row * S_DIM);
    float4 x0 = sr[lane];
    float4 x1 = sr[lane + 32];

    float m = fmaxf(fmaxf(fmaxf(x0.x, x0.y), fmaxf(x0.z, x0.w)),
                    fmaxf(fmaxf(x1.x, x1.y), fmaxf(x1.z, x1.w)));
    #pragma unroll
    for (int o = 16; o > 0; o >>= 1) m = fmaxf(m, __shfl_xor_sync(0xffffffffu, m, o));

    const int4* mp = (const int4*)(mask + b * S_DIM);
    int4 k0 = mp[lane];
    int4 k1 = mp[lane + 32];

    float4 e0, e1;
    e0.x = __expf(x0.x - m) * (1.0f - (float)k0.x);
    e0.y = __expf(x0.y - m) * (1.0f - (float)k0.y);
    e0.z = __expf(x0.z - m) * (1.0f - (float)k0.z);
    e0.w = __expf(x0.w - m) * (1.0f - (float)k0.w);
    e1.x = __expf(x1.x - m) * (1.0f - (float)k1.x);
    e1.y = __expf(x1.y - m) * (1.0f - (float)k1.y);
    e1.z = __expf(x1.z - m) * (1.0f - (float)k1.z);
    e1.w = __expf(x1.w - m) * (1.0f - (float)k1.w);

    float sum = e0.x + e0.y + e0.z + e0.w + e1.x + e1.y + e1.z + e1.w;
    #pragma unroll
    for (int o = 16; o > 0; o >>= 1) sum += __shfl_xor_sync(0xffffffffu, sum, o);

    float inv = 1.0f / sum;
    e0.x *= inv; e0.y *= inv; e0.z *= inv; e0.w *= inv;
    e1.x *= inv; e1.y *= inv; e1.z *= inv; e1.w *= inv;

    __nv_bfloat16* hp = at_hi + (long)row * S_DIM;
    __nv_bfloat16* lp = at_lo + (long)row * S_DIM;
    wr_split2(hp, lp, 4 * lane,       e0.x, e0.y);
    wr_split2(hp, lp, 4 * lane + 2,   e0.z, e0.w);
    wr_split2(hp, lp, 128 + 4 * lane, e1.x, e1.y);
    wr_split2(hp, lp, 130 + 4 * lane, e1.z, e1.w);

    if (attn_out) {
        float4* ao = (float4*)(attn_out + (long)row * S_DIM);
        ao[lane]      = e0;
        ao[lane + 32] = e1;
    }
}

// ---------------- launch ----------------
extern "C" void kernel_launch(void* const* d_in, const int* in_sizes, int n_in,
                              void* d_out, int out_size)
{
    const float* output  = (const float*)d_in[0];
    const float* context = (const float*)d_in[1];
    const int*   mask    = (const int*)d_in[2];
    const float* Wq      = (const float*)d_in[3];
    const float* bq      = (const float*)d_in[4];
    const float* Wc      = (const float*)d_in[5];
    const float* v       = (const float*)d_in[6];
    const float* Wout    = (const float*)d_in[7];
    const float* bout    = (const float*)d_in[8];

    float *wq, *uh, *score;
    cudaGetSymbolAddress((void**)&wq,    g_wq);
    cudaGetSymbolAddress((void**)&uh,    g_uh);
    cudaGetSymbolAddress((void**)&score, g_score);

    __nv_bfloat16 *out_hi, *out_lo, *ctx_hi, *ctx_lo, *ctxT_hi, *ctxT_lo;
    __nv_bfloat16 *WqT_hi, *WqT_lo, *WcT_hi, *WcT_lo, *WoT_hi, *WoT_lo;
    __nv_bfloat16 *at_hi, *at_lo, *mx_hi, *mx_lo;
    cudaGetSymbolAddress((void**)&out_hi,  g_out_hi);
    cudaGetSymbolAddress((void**)&out_lo,  g_out_lo);
    cudaGetSymbolAddress((void**)&ctx_hi,  g_ctx_hi);
    cudaGetSymbolAddress((void**)&ctx_lo,  g_ctx_lo);
    cudaGetSymbolAddress((void**)&ctxT_hi, g_ctxT_hi);
    cudaGetSymbolAddress((void**)&ctxT_lo, g_ctxT_lo);
    cudaGetSymbolAddress((void**)&WqT_hi,  g_WqT_hi);
    cudaGetSymbolAddress((void**)&WqT_lo,  g_WqT_lo);
    cudaGetSymbolAddress((void**)&WcT_hi,  g_WcT_hi);
    cudaGetSymbolAddress((void**)&WcT_lo,  g_WcT_lo);
    cudaGetSymbolAddress((void**)&WoT_hi,  g_WoT_hi);
    cudaGetSymbolAddress((void**)&WoT_lo,  g_WoT_lo);
    cudaGetSymbolAddress((void**)&at_hi,   g_at_hi);
    cudaGetSymbolAddress((void**)&at_lo,   g_at_lo);
    cudaGetSymbolAddress((void**)&mx_hi,   g_mx_hi);
    cudaGetSymbolAddress((void**)&mx_lo,   g_mx_lo);

    float* out = (float*)d_out;
    const int out_elems  = B_DIM * T_DIM * D_DIM;   // 524288
    const int attn_elems = B_DIM * T_DIM * S_DIM;   // 262144
    float* attn_out = (out_size >= out_elems + attn_elems) ? (out + out_elems) : nullptr;

    const dim3 tb(32, 8);
    const long sCtxT = (long)S_DIM * D_DIM;

    // ---- fork side streams off the capture (default) stream ----
    cudaEventRecord(evFork, 0);
    cudaStreamWaitEvent(s1, evFork, 0);
    cudaStreamWaitEvent(s2, evFork, 0);
    cudaStreamWaitEvent(s3, evFork, 0);

    // s1: uh branch (Wc^T split, context split, uh GEMM)
    splitT_kernel<<<dim3(16, 16, 1), tb, 0, s1>>>(Wc, WcT_hi, WcT_lo, 512, 512, 0, 0);
    split_kernel<<<256, 256, 0, s1>>>(context, ctx_hi, ctx_lo, 524288);
    gemm_bf16s<<<dim3(8, 16, 1), 256, 0, s1>>>(ctx_hi, ctx_lo, nullptr, nullptr,
                                               WcT_hi, WcT_lo, uh, nullptr, nullptr,
                                               512, 512, 512, nullptr, 0, 0, 0);
    cudaEventRecord(ev1, s1);

    // s2: context^T split (for mix GEMM)
    splitT_kernel<<<dim3(16, 8, 4), tb, 0, s2>>>(context, ctxT_hi, ctxT_lo, 256, 512,
                                                 sCtxT, sCtxT);
    cudaEventRecord(ev2, s2);

    // s3: Wout^T split (for final GEMM)
    splitT_kernel<<<dim3(16, 32, 1), tb, 0, s3>>>(Wout, WoT_hi, WoT_lo, 1024, 512, 0, 0);
    cudaEventRecord(ev3, s3);

    // s0 (critical path): Wq^T split, output split, wq GEMM
    splitT_kernel<<<dim3(16, 16, 1), tb>>>(Wq, WqT_hi, WqT_lo, 512, 512, 0, 0);
    split_kernel<<<256, 256>>>(output, out_hi, out_lo, 524288);
    gemm_bf16s<<<dim3(8, 16, 1), 256>>>(out_hi, out_lo, nullptr, nullptr,
                                        WqT_hi, WqT_lo, wq, nullptr, nullptr,
                                        512, 512, 512, bq, 0, 0, 0);

    // join uh branch, then score + softmax
    cudaStreamWaitEvent(0, ev1, 0);
    score_kernel<<<dim3(8, 8, 4), 256>>>(wq, uh, v, score);
    softmax_kernel<<<128, 256>>>(score, mask, at_hi, at_lo, attn_out);

    // join ctxT, mix GEMM with fused hi/lo split epilogue
    cudaStreamWaitEvent(0, ev2, 0);
    gemm_bf16s<<<dim3(8, 4, 4), 256>>>(at_hi, at_lo, nullptr, nullptr,
                                       ctxT_hi, ctxT_lo, nullptr, mx_hi, mx_lo,
                                       512, 256, 256, nullptr,
                                       (long)T_DIM * S_DIM, sCtxT, (long)T_DIM * D_DIM);

    // join WoT, final GEMM: out = [mix | output] @ Wout + bout
    cudaStreamWaitEvent(0, ev3, 0);
    gemm_bf16s<<<dim3(8, 16, 1), 256>>>(mx_hi, mx_lo, out_hi, out_lo,
                                        WoT_hi, WoT_lo, out, nullptr, nullptr,
                                        512, 512, 1024, bout, 0, 0, 0);
}

// round 12
// speedup vs baseline: 2.0383x; 1.0399x over previous
#include <cuda_runtime.h>
#include <cuda_bf16.h>
#include <cstdint>

#define B_DIM 4
#define T_DIM 256
#define S_DIM 256
#define D_DIM 512

// ---------------- fp32 scratch ----------------
__device__ float g_wq[B_DIM * T_DIM * D_DIM];     // 2 MB
__device__ float g_uh[B_DIM * S_DIM * D_DIM];     // 2 MB
__device__ float g_score[B_DIM * T_DIM * S_DIM];  // 1 MB

// ---------------- bf16 split scratch ----------------
__device__ __nv_bfloat16 g_out_hi[524288],  g_out_lo[524288];    // output [1024,512]
__device__ __nv_bfloat16 g_ctx_hi[524288],  g_ctx_lo[524288];    // context [1024,512]
__device__ __nv_bfloat16 g_ctxT_hi[524288], g_ctxT_lo[524288];   // context^T [4][512][256]
__device__ __nv_bfloat16 g_WqT_hi[262144],  g_WqT_lo[262144];    // Wq^T [512,512]
__device__ __nv_bfloat16 g_WcT_hi[262144],  g_WcT_lo[262144];    // Wc^T [512,512]
__device__ __nv_bfloat16 g_WoT_hi[524288],  g_WoT_lo[524288];    // Wout^T [512,1024]
__device__ __nv_bfloat16 g_at_hi[262144],   g_at_lo[262144];     // attn [1024,256]
__device__ __nv_bfloat16 g_mx_hi[524288],   g_mx_lo[524288];     // mix [1024,512]

// ---------------- streams/events for graph fork-join (created before main) ----------
static cudaStream_t s1;
static cudaEvent_t  evFork, ev1;
struct StreamInit {
    StreamInit() {
        cudaStreamCreateWithFlags(&s1, cudaStreamNonBlocking);
        cudaEventCreateWithFlags(&evFork, cudaEventDisableTiming);
        cudaEventCreateWithFlags(&ev1, cudaEventDisableTiming);
    }
};
static StreamInit g_streams_init;

__device__ __forceinline__ float tanh_fast(float x) {
    float y;
    asm("tanh.approx.f32 %0, %1;" : "=f"(y) : "f"(x));
    return y;
}

// ---------------- fused staging: all splits + transposes in ONE launch ------------
__device__ __forceinline__ void do_split_block(
    const float* __restrict__ src,
    __nv_bfloat16* __restrict__ hi, __nv_bfloat16* __restrict__ lo, int blk)
{
    int i = blk * 1024 + threadIdx.x * 4;
    float4 x = *(const float4*)(src + i);
    __nv_bfloat16 h0 = __float2bfloat16(x.x);
    __nv_bfloat16 h1 = __float2bfloat16(x.y);
    __nv_bfloat16 h2 = __float2bfloat16(x.z);
    __nv_bfloat16 h3 = __float2bfloat16(x.w);
    __nv_bfloat162 hh0; hh0.x = h0; hh0.y = h1;
    __nv_bfloat162 hh1; hh1.x = h2; hh1.y = h3;
    __nv_bfloat162 ll0;
    ll0.x = __float2bfloat16(x.x - __bfloat162float(h0));
    ll0.y = __float2bfloat16(x.y - __bfloat162float(h1));
    __nv_bfloat162 ll1;
    ll1.x = __float2bfloat16(x.z - __bfloat162float(h2));
    ll1.y = __float2bfloat16(x.w - __bfloat162float(h3));
    *(__nv_bfloat162*)(hi + i)     = hh0;
    *(__nv_bfloat162*)(hi + i + 2) = hh1;
    *(__nv_bfloat162*)(lo + i)     = ll0;
    *(__nv_bfloat162*)(lo + i + 2) = ll1;
}

// Transpose-split for one 32x32 tile; shared tile passed in from kernel scope.
__device__ __forceinline__ void do_splitT_block(
    float (*tile)[33],
    const float* __restrict__ src,
    __nv_bfloat16* __restrict__ hiT, __nv_bfloat16* __restrict__ loT,
    int R, int C, int bx, int by)
{
    const int r0 = by * 32, c0 = bx * 32;
    const int tx = threadIdx.x & 31, ty = threadIdx.x >> 5;   // 32 x 8

    #pragma unroll
    for (int i = 0; i < 4; i++)
        tile[ty + i * 8][tx] = src[(long)(r0 + ty + i * 8) * C + c0 + tx];
    __syncthreads();
    #pragma unroll
    for (int i = 0; i < 4; i++) {
        int cr = c0 + ty + i * 8;
        float x = tile[tx][ty + i * 8];
        __nv_bfloat16 h = __float2bfloat16(x);
        hiT[(long)cr * R + r0 + tx] = h;
        loT[(long)cr * R + r0 + tx] = __float2bfloat16(x - __bfloat162float(h));
    }
}

__global__ __launch_bounds__(256) void stage_all(
    const float* __restrict__ output, const float* __restrict__ context,
    const float* __restrict__ Wq, const float* __restrict__ Wc,
    const float* __restrict__ Wout)
{
    __shared__ float tile[32][33];       // single smem instance, kernel scope
    const int j = blockIdx.x;
    if (j < 512) {                       // split output (524288 / 1024)
        do_split_block(output, g_out_hi, g_out_lo, j);
    } else if (j < 1024) {               // split context
        do_split_block(context, g_ctx_hi, g_ctx_lo, j - 512);
    } else if (j < 1280) {               // splitT Wq [512,512] -> [512,512]
        int k = j - 1024;
        do_splitT_block(tile, Wq, g_WqT_hi, g_WqT_lo, 512, 512, k & 15, k >> 4);
    } else if (j < 1536) {               // splitT Wc
        int k = j - 1280;
        do_splitT_block(tile, Wc, g_WcT_hi, g_WcT_lo, 512, 512, k & 15, k >> 4);
    } else if (j < 2048) {               // splitT Wout [1024,512] -> [512,1024]
        int k = j - 1536;
        do_splitT_block(tile, Wout, g_WoT_hi, g_WoT_lo, 1024, 512, k & 15, k >> 4);
    } else {                             // splitT context per batch [256,512] -> [512,256]
        int k = j - 2048;
        int z = k >> 7, rem = k & 127;
        const long s = (long)S_DIM * D_DIM;
        do_splitT_block(tile, context + z * s, g_ctxT_hi + z * s, g_ctxT_lo + z * s,
                        256, 512, rem & 15, rem >> 4);
    }
}

// ---------------- split-bf16 tensor-core GEMM (256 thr, 8 warps, 64x64 tile) ----
#define MMA_BF16(d, a, b)                                                     \
    asm volatile("mma.sync.aligned.m16n8k16.row.col.f32.bf16.bf16.f32 "       \
                 "{%0,%1,%2,%3},{%4,%5,%6,%7},{%8,%9},{%0,%1,%2,%3};"         \
                 : "+f"((d)[0]), "+f"((d)[1]), "+f"((d)[2]), "+f"((d)[3])     \
                 : "r"((a)[0]), "r"((a)[1]), "r"((a)[2]), "r"((a)[3]),        \
                   "r"((b)[0]), "r"((b)[1]))

__global__ __launch_bounds__(256) void gemm_bf16s(
    const __nv_bfloat16* __restrict__ Ahi, const __nv_bfloat16* __restrict__ Alo,
    const __nv_bfloat16* __restrict__ A2hi, const __nv_bfloat16* __restrict__ A2lo,
    const __nv_bfloat16* __restrict__ BThi, const __nv_bfloat16* __restrict__ BTlo,
    float* __restrict__ C,
    __nv_bfloat16* __restrict__ Chi, __nv_bfloat16* __restrict__ Clo,
    int N, int Ka, int Ktot, const float* __restrict__ bias,
    long sA, long sB, long sC)
{
    Ahi  += (long)blockIdx.z * sA;  Alo  += (long)blockIdx.z * sA;
    BThi += (long)blockIdx.z * sB;  BTlo += (long)blockIdx.z * sB;
    if (C)   C   += (long)blockIdx.z * sC;
    if (Chi) { Chi += (long)blockIdx.z * sC; Clo += (long)blockIdx.z * sC; }

    __shared__ __align__(16) __nv_bfloat16 As[2][2][64 * 24];
    __shared__ __align__(16) __nv_bfloat16 Bs[2][2][64 * 24];

    const int tid  = threadIdx.x;
    const int lane = tid & 31;
    const int wid  = tid >> 5;
    const int wm   = wid & 1;
    const int wn   = wid >> 1;
    const int m0   = blockIdx.y * 64;
    const int n0   = blockIdx.x * 64;
    const int g    = lane >> 2;
    const int t    = lane & 3;
    const int arow = tid >> 2;
    const int part = (tid >> 1) & 1;
    const int seg  = tid & 1;

    const int Kb = Ktot - Ka;
    const int KT = Ktot >> 4;

    int4 ra, rb;

#define LDG(kt) {                                                              \
        int gk = (kt) << 4;                                                    \
        const __nv_bfloat16 *ap;                                               \
        if (A2hi && gk >= Ka) {                                                \
            long off = (long)(m0 + arow) * Kb + (gk - Ka) + seg * 8;           \
            ap = (part ? A2lo : A2hi) + off;                                   \
        } else {                                                               \
            long off = (long)(m0 + arow) * Ka + gk + seg * 8;                  \
            ap = (part ? Alo : Ahi) + off;                                     \
        }                                                                      \
        ra = *(const int4*)ap;                                                 \
        long boff = (long)(n0 + arow) * Ktot + gk + seg * 8;                   \
        rb = *(const int4*)((part ? BTlo : BThi) + boff);                      \
    }

#define STS(bf) {                                                              \
        int so = arow * 24 + seg * 8;                                          \
        *(int4*)&As[bf][part][so] = ra;                                        \
        *(int4*)&Bs[bf][part][so] = rb;                                        \
    }

    float acc[2][2][4] = {};

    LDG(0); STS(0);
    __syncthreads();

    for (int kt = 0; kt < KT; kt++) {
        const int buf = kt & 1;
        if (kt + 1 < KT) LDG(kt + 1);

        uint32_t ah[2][4], al[2][4], bh[2][2], bl[2][2];
        const __nv_bfloat16* pah = &As[buf][0][0];
        const __nv_bfloat16* pal = &As[buf][1][0];
        const __nv_bfloat16* pbh = &Bs[buf][0][0];
        const __nv_bfloat16* pbl = &Bs[buf][1][0];

        #pragma unroll
        for (int mi = 0; mi < 2; mi++) {
            int base = (wm * 32 + mi * 16 + g) * 24 + 2 * t;
            ah[mi][0] = *(const uint32_t*)(pah + base);
            ah[mi][1] = *(const uint32_t*)(pah + base + 8 * 24);
            ah[mi][2] = *(const uint32_t*)(pah + base + 8);
            ah[mi][3] = *(const uint32_t*)(pah + base + 8 * 24 + 8);
            al[mi][0] = *(const uint32_t*)(pal + base);
            al[mi][1] = *(const uint32_t*)(pal + base + 8 * 24);
            al[mi][2] = *(const uint32_t*)(pal + base + 8);
            al[mi][3] = *(const uint32_t*)(pal + base + 8 * 24 + 8);
        }
        #pragma unroll
        for (int nj = 0; nj < 2; nj++) {
            int base = (wn * 16 + nj * 8 + g) * 24 + 2 * t;
            bh[nj][0] = *(const uint32_t*)(pbh + base);
            bh[nj][1] = *(const uint32_t*)(pbh + base + 8);
            bl[nj][0] = *(const uint32_t*)(pbl + base);
            bl[nj][1] = *(const uint32_t*)(pbl + base + 8);
        }

        #pragma unroll
        for (int mi = 0; mi < 2; mi++)
            #pragma unroll
            for (int nj = 0; nj < 2; nj++) {
                MMA_BF16(acc[mi][nj], ah[mi], bh[nj]);
                MMA_BF16(acc[mi][nj], ah[mi], bl[nj]);
                MMA_BF16(acc[mi][nj], al[mi], bh[nj]);
            }

        if (kt + 1 < KT) STS(buf ^ 1);
        __syncthreads();
    }

    #pragma unroll
    for (int mi = 0; mi < 2; mi++)
        #pragma unroll
        for (int nj = 0; nj < 2; nj++) {
            int r = m0 + wm * 32 + mi * 16 + g;
            int c = n0 + wn * 16 + nj * 8 + 2 * t;
            float b0 = 0.f, b1 = 0.f;
            if (bias) { b0 = bias[c]; b1 = bias[c + 1]; }
            float v0 = acc[mi][nj][0] + b0, v1 = acc[mi][nj][1] + b1;
            float v2 = acc[mi][nj][2] + b0, v3 = acc[mi][nj][3] + b1;
            if (Chi) {
                __nv_bfloat162 hh0, ll0, hh1, ll1;
                hh0.x = __float2bfloat16(v0); hh0.y = __float2bfloat16(v1);
                ll0.x = __float2bfloat16(v0 - __bfloat162float(hh0.x));
                ll0.y = __float2bfloat16(v1 - __bfloat162float(hh0.y));
                hh1.x = __float2bfloat16(v2); hh1.y = __float2bfloat16(v3);
                ll1.x = __float2bfloat16(v2 - __bfloat162float(hh1.x));
                ll1.y = __float2bfloat16(v3 - __bfloat162float(hh1.y));
                *(__nv_bfloat162*)&Chi[(long)r * N + c]       = hh0;
                *(__nv_bfloat162*)&Clo[(long)r * N + c]       = ll0;
                *(__nv_bfloat162*)&Chi[(long)(r + 8) * N + c] = hh1;
                *(__nv_bfloat162*)&Clo[(long)(r + 8) * N + c] = ll1;
            } else {
                float2 o0; o0.x = v0; o0.y = v1;
                float2 o1; o1.x = v2; o1.y = v3;
                *(float2*)&C[(long)r * N + c]       = o0;
                *(float2*)&C[(long)(r + 8) * N + c] = o1;
            }
        }
#undef LDG
#undef STS
}

// ---------------- score kernel ----------------
__global__ __launch_bounds__(256) void score_kernel(
    const float* __restrict__ wq, const float* __restrict__ uh,
    const float* __restrict__ v, float* __restrict__ score)
{
    const int b  = blockIdx.z;
    const int t0 = blockIdx.y * 32;
    const int s0 = blockIdx.x * 32;

    __shared__ float wq_s[64][34];
    __shared__ float uh_s[64][34];
    __shared__ float v_s[64];

    const int tid  = threadIdx.x;
    const int tt   = tid >> 4;
    const int ss   = tid & 15;
    const int lrow = tid >> 3;
    const int lcol = (tid & 7) * 8;

    const float* wq_b = wq + ((long)b * T_DIM + t0) * D_DIM;
    const float* uh_b = uh + ((long)b * S_DIM + s0) * D_DIM;

    float acc00 = 0.f, acc01 = 0.f, acc10 = 0.f, acc11 = 0.f;

    for (int d0 = 0; d0 < D_DIM; d0 += 64) {
        float4 w0 = *(const float4*)&wq_b[(long)lrow * D_DIM + d0 + lcol];
        float4 w1 = *(const float4*)&wq_b[(long)lrow * D_DIM + d0 + lcol + 4];
        float4 u0 = *(const float4*)&uh_b[(long)lrow * D_DIM + d0 + lcol];
        float4 u1 = *(const float4*)&uh_b[(long)lrow * D_DIM + d0 + lcol + 4];

        wq_s[lcol + 0][lrow] = w0.x; wq_s[lcol + 1][lrow] = w0.y;
        wq_s[lcol + 2][lrow] = w0.z; wq_s[lcol + 3][lrow] = w0.w;
        wq_s[lcol + 4][lrow] = w1.x; wq_s[lcol + 5][lrow] = w1.y;
        wq_s[lcol + 6][lrow] = w1.z; wq_s[lcol + 7][lrow] = w1.w;
        uh_s[lcol + 0][lrow] = u0.x; uh_s[lcol + 1][lrow] = u0.y;
        uh_s[lcol + 2][lrow] = u0.z; uh_s[lcol + 3][lrow] = u0.w;
        uh_s[lcol + 4][lrow] = u1.x; uh_s[lcol + 5][lrow] = u1.y;
        uh_s[lcol + 6][lrow] = u1.z; uh_s[lcol + 7][lrow] = u1.w;
        if (tid < 16) *(float4*)&v_s[tid * 4] = *(const float4*)&v[d0 + tid * 4];
        __syncthreads();

        #pragma unroll 16
        for (int d = 0; d < 64; d++) {
            float2 a = *(const float2*)&wq_s[d][tt * 2];
            float2 u = *(const float2*)&uh_s[d][ss * 2];
            float vd = v_s[d];
            acc00 = fmaf(vd, tanh_fast(a.x + u.x), acc00);
            acc01 = fmaf(vd, tanh_fast(a.x + u.y), acc01);
            acc10 = fmaf(vd, tanh_fast(a.y + u.x), acc10);
            acc11 = fmaf(vd, tanh_fast(a.y + u.y), acc11);
        }
        __syncthreads();
    }

    long base = ((long)b * T_DIM + t0 + tt * 2) * S_DIM + s0 + ss * 2;
    score[base]             = acc00;
    score[base + 1]         = acc01;
    score[base + S_DIM]     = acc10;
    score[base + S_DIM + 1] = acc11;
}

// ---------------- masked softmax + fused attn hi/lo split ----------------
__device__ __forceinline__ void wr_split2(
    __nv_bfloat16* hp, __nv_bfloat16* lp, int c, float a, float b)
{
    __nv_bfloat16 h0 = __float2bfloat16(a);
    __nv_bfloat16 h1 = __float2bfloat16(b);
    __nv_bfloat162 hh; hh.x = h0; hh.y = h1;
    __nv_bfloat162 ll;
    ll.x = __float2bfloat16(a - __bfloat162float(h0));
    ll.y = __float2bfloat16(b - __bfloat162float(h1));
    *(__nv_bfloat162*)(hp + c) = hh;
    *(__nv_bfloat162*)(lp + c) = ll;
}

__global__ __launch_bounds__(256) void softmax_kernel(
    const float* __restrict__ score, const int* __restrict__ mask,
    __nv_bfloat16* __restrict__ at_hi, __nv_bfloat16* __restrict__ at_lo,
    float* __restrict__ attn_out)
{
    const int lane = threadIdx.x & 31;
    const int w    = threadIdx.x >> 5;
    const int row  = blockIdx.x * 8 + w;    // b*T + t
    const int b    = row >> 8;              // T = 256

    const float4* sr = (const float4*)(score + (long)row * S_DIM);
    float4 x0 = sr[lane];
    float4 x1 = sr[lane + 32];

    float m = fmaxf(fmaxf(fmaxf(x0.x, x0.y), fmaxf(x0.z, x0.w)),
                    fmaxf(fmaxf(x1.x, x1.y), fmaxf(x1.z, x1.w)));
    #pragma unroll
    for (int o = 16; o > 0; o >>= 1) m = fmaxf(m, __shfl_xor_sync(0xffffffffu, m, o));

    const int4* mp = (const int4*)(mask + b * S_DIM);
    int4 k0 = mp[lane];
    int4 k1 = mp[lane + 32];

    float4 e0, e1;
    e0.x = __expf(x0.x - m) * (1.0f - (float)k0.x);
    e0.y = __expf(x0.y - m) * (1.0f - (float)k0.y);
    e0.z = __expf(x0.z - m) * (1.0f - (float)k0.z);
    e0.w = __expf(x0.w - m) * (1.0f - (float)k0.w);
    e1.x = __expf(x1.x - m) * (1.0f - (float)k1.x);
    e1.y = __expf(x1.y - m) * (1.0f - (float)k1.y);
    e1.z = __expf(x1.z - m) * (1.0f - (float)k1.z);
    e1.w = __expf(x1.w - m) * (1.0f - (float)k1.w);

    float sum = e0.x + e0.y + e0.z + e0.w + e1.x + e1.y + e1.z + e1.w;
    #pragma unroll
    for (int o = 16; o > 0; o >>= 1) sum += __shfl_xor_sync(0xffffffffu, sum, o);

    float inv = 1.0f / sum;
    e0.x *= inv; e0.y *= inv; e0.z *= inv; e0.w *= inv;
    e1.x *= inv; e1.y *= inv; e1.z *= inv; e1.w *= inv;

    __nv_bfloat16* hp = at_hi + (long)row * S_DIM;
    __nv_bfloat16* lp = at_lo + (long)row * S_DIM;
    wr_split2(hp, lp, 4 * lane,       e0.x, e0.y);
    wr_split2(hp, lp, 4 * lane + 2,   e0.z, e0.w);
    wr_split2(hp, lp, 128 + 4 * lane, e1.x, e1.y);
    wr_split2(hp, lp, 130 + 4 * lane, e1.z, e1.w);

    if (attn_out) {
        float4* ao = (float4*)(attn_out + (long)row * S_DIM);
        ao[lane]      = e0;
        ao[lane + 32] = e1;
    }
}

// ---------------- launch ----------------
extern "C" void kernel_launch(void* const* d_in, const int* in_sizes, int n_in,
                              void* d_out, int out_size)
{
    const float* output  = (const float*)d_in[0];
    const float* context = (const float*)d_in[1];
    const int*   mask    = (const int*)d_in[2];
    const float* Wq      = (const float*)d_in[3];
    const float* bq      = (const float*)d_in[4];
    const float* Wc      = (const float*)d_in[5];
    const float* v       = (const float*)d_in[6];
    const float* Wout    = (const float*)d_in[7];
    const float* bout    = (const float*)d_in[8];

    float *wq, *uh, *score;
    cudaGetSymbolAddress((void**)&wq,    g_wq);
    cudaGetSymbolAddress((void**)&uh,    g_uh);
    cudaGetSymbolAddress((void**)&score, g_score);

    __nv_bfloat16 *out_hi, *out_lo, *ctx_hi, *ctx_lo, *ctxT_hi, *ctxT_lo;
    __nv_bfloat16 *WqT_hi, *WqT_lo, *WcT_hi, *WcT_lo, *WoT_hi, *WoT_lo;
    __nv_bfloat16 *at_hi, *at_lo, *mx_hi, *mx_lo;
    cudaGetSymbolAddress((void**)&out_hi,  g_out_hi);
    cudaGetSymbolAddress((void**)&out_lo,  g_out_lo);
    cudaGetSymbolAddress((void**)&ctx_hi,  g_ctx_hi);
    cudaGetSymbolAddress((void**)&ctx_lo,  g_ctx_lo);
    cudaGetSymbolAddress((void**)&ctxT_hi, g_ctxT_hi);
    cudaGetSymbolAddress((void**)&ctxT_lo, g_ctxT_lo);
    cudaGetSymbolAddress((void**)&WqT_hi,  g_WqT_hi);
    cudaGetSymbolAddress((void**)&WqT_lo,  g_WqT_lo);
    cudaGetSymbolAddress((void**)&WcT_hi,  g_WcT_hi);
    cudaGetSymbolAddress((void**)&WcT_lo,  g_WcT_lo);
    cudaGetSymbolAddress((void**)&WoT_hi,  g_WoT_hi);
    cudaGetSymbolAddress((void**)&WoT_lo,  g_WoT_lo);
    cudaGetSymbolAddress((void**)&at_hi,   g_at_hi);
    cudaGetSymbolAddress((void**)&at_lo,   g_at_lo);
    cudaGetSymbolAddress((void**)&mx_hi,   g_mx_hi);
    cudaGetSymbolAddress((void**)&mx_lo,   g_mx_lo);

    float* out = (float*)d_out;
    const int out_elems  = B_DIM * T_DIM * D_DIM;   // 524288
    const int attn_elems = B_DIM * T_DIM * S_DIM;   // 262144
    float* attn_out = (out_size >= out_elems + attn_elems) ? (out + out_elems) : nullptr;

    const long sCtxT = (long)S_DIM * D_DIM;

    // 1) all staging in one wide launch
    stage_all<<<2560, 256>>>(output, context, Wq, Wc, Wout);

    // 2) wq GEMM (s0) and uh GEMM (s1) concurrently
    cudaEventRecord(evFork, 0);
    cudaStreamWaitEvent(s1, evFork, 0);

    gemm_bf16s<<<dim3(8, 16, 1), 256>>>(out_hi, out_lo, nullptr, nullptr,
                                        WqT_hi, WqT_lo, wq, nullptr, nullptr,
                                        512, 512, 512, bq, 0, 0, 0);
    gemm_bf16s<<<dim3(8, 16, 1), 256, 0, s1>>>(ctx_hi, ctx_lo, nullptr, nullptr,
                                               WcT_hi, WcT_lo, uh, nullptr, nullptr,
                                               512, 512, 512, nullptr, 0, 0, 0);
    cudaEventRecord(ev1, s1);
    cudaStreamWaitEvent(0, ev1, 0);

    // 3) score -> softmax -> mix GEMM (fused split epilogue) -> final GEMM
    score_kernel<<<dim3(8, 8, 4), 256>>>(wq, uh, v, score);
    softmax_kernel<<<128, 256>>>(score, mask, at_hi, at_lo, attn_out);
    gemm_bf16s<<<dim3(8, 4, 4), 256>>>(at_hi, at_lo, nullptr, nullptr,
                                       ctxT_hi, ctxT_lo, nullptr, mx_hi, mx_lo,
                                       512, 256, 256, nullptr,
                                       (long)T_DIM * S_DIM, sCtxT, (long)T_DIM * D_DIM);
    gemm_bf16s<<<dim3(8, 16, 1), 256>>>(mx_hi, mx_lo, out_hi, out_lo,
                                        WoT_hi, WoT_lo, out, nullptr, nullptr,
                                        512, 512, 1024, bout, 0, 0, 0);
}

// round 13
// speedup vs baseline: 2.0532x; 1.0073x over previous
#include <cuda_runtime.h>
#include <cuda_bf16.h>
#include <cstdint>

#define B_DIM 4
#define T_DIM 256
#define S_DIM 256
#define D_DIM 512

// ---------------- fp32 scratch ----------------
__device__ float g_wq[B_DIM * T_DIM * D_DIM];       // 2 MB
__device__ float g_uh[B_DIM * S_DIM * D_DIM];       // 2 MB
__device__ float g_score2[2][B_DIM * T_DIM * S_DIM]; // 2 MB (two d-halves)

// ---------------- bf16 split scratch ----------------
__device__ __nv_bfloat16 g_out_hi[524288],  g_out_lo[524288];    // output [1024,512]
__device__ __nv_bfloat16 g_ctx_hi[524288],  g_ctx_lo[524288];    // context [1024,512]
__device__ __nv_bfloat16 g_ctxT_hi[524288], g_ctxT_lo[524288];   // context^T [4][512][256]
__device__ __nv_bfloat16 g_WqT_hi[262144],  g_WqT_lo[262144];    // Wq^T [512,512]
__device__ __nv_bfloat16 g_WcT_hi[262144],  g_WcT_lo[262144];    // Wc^T [512,512]
__device__ __nv_bfloat16 g_WoT_hi[524288],  g_WoT_lo[524288];    // Wout^T [512,1024]
__device__ __nv_bfloat16 g_at_hi[262144],   g_at_lo[262144];     // attn [1024,256]
__device__ __nv_bfloat16 g_mx_hi[524288],   g_mx_lo[524288];     // mix [1024,512]

// ---------------- streams/events for graph fork-join (created before main) ----------
static cudaStream_t s1;
static cudaEvent_t  evFork, ev1;
struct StreamInit {
    StreamInit() {
        cudaStreamCreateWithFlags(&s1, cudaStreamNonBlocking);
        cudaEventCreateWithFlags(&evFork, cudaEventDisableTiming);
        cudaEventCreateWithFlags(&ev1, cudaEventDisableTiming);
    }
};
static StreamInit g_streams_init;

__device__ __forceinline__ float tanh_fast(float x) {
    float y;
    asm("tanh.approx.f32 %0, %1;" : "=f"(y) : "f"(x));
    return y;
}

// ---------------- fused staging: all splits + transposes in ONE launch ------------
__device__ __forceinline__ void do_split_block(
    const float* __restrict__ src,
    __nv_bfloat16* __restrict__ hi, __nv_bfloat16* __restrict__ lo, int blk)
{
    int i = blk * 1024 + threadIdx.x * 4;
    float4 x = *(const float4*)(src + i);
    __nv_bfloat16 h0 = __float2bfloat16(x.x);
    __nv_bfloat16 h1 = __float2bfloat16(x.y);
    __nv_bfloat16 h2 = __float2bfloat16(x.z);
    __nv_bfloat16 h3 = __float2bfloat16(x.w);
    __nv_bfloat162 hh0; hh0.x = h0; hh0.y = h1;
    __nv_bfloat162 hh1; hh1.x = h2; hh1.y = h3;
    __nv_bfloat162 ll0;
    ll0.x = __float2bfloat16(x.x - __bfloat162float(h0));
    ll0.y = __float2bfloat16(x.y - __bfloat162float(h1));
    __nv_bfloat162 ll1;
    ll1.x = __float2bfloat16(x.z - __bfloat162float(h2));
    ll1.y = __float2bfloat16(x.w - __bfloat162float(h3));
    *(__nv_bfloat162*)(hi + i)     = hh0;
    *(__nv_bfloat162*)(hi + i + 2) = hh1;
    *(__nv_bfloat162*)(lo + i)     = ll0;
    *(__nv_bfloat162*)(lo + i + 2) = ll1;
}

__device__ __forceinline__ void do_splitT_block(
    float (*tile)[33],
    const float* __restrict__ src,
    __nv_bfloat16* __restrict__ hiT, __nv_bfloat16* __restrict__ loT,
    int R, int C, int bx, int by)
{
    const int r0 = by * 32, c0 = bx * 32;
    const int tx = threadIdx.x & 31, ty = threadIdx.x >> 5;   // 32 x 8

    #pragma unroll
    for (int i = 0; i < 4; i++)
        tile[ty + i * 8][tx] = src[(long)(r0 + ty + i * 8) * C + c0 + tx];
    __syncthreads();
    #pragma unroll
    for (int i = 0; i < 4; i++) {
        int cr = c0 + ty + i * 8;
        float x = tile[tx][ty + i * 8];
        __nv_bfloat16 h = __float2bfloat16(x);
        hiT[(long)cr * R + r0 + tx] = h;
        loT[(long)cr * R + r0 + tx] = __float2bfloat16(x - __bfloat162float(h));
    }
}

__global__ __launch_bounds__(256) void stage_all(
    const float* __restrict__ output, const float* __restrict__ context,
    const float* __restrict__ Wq, const float* __restrict__ Wc,
    const float* __restrict__ Wout)
{
    __shared__ float tile[32][33];
    const int j = blockIdx.x;
    if (j < 512) {
        do_split_block(output, g_out_hi, g_out_lo, j);
    } else if (j < 1024) {
        do_split_block(context, g_ctx_hi, g_ctx_lo, j - 512);
    } else if (j < 1280) {
        int k = j - 1024;
        do_splitT_block(tile, Wq, g_WqT_hi, g_WqT_lo, 512, 512, k & 15, k >> 4);
    } else if (j < 1536) {
        int k = j - 1280;
        do_splitT_block(tile, Wc, g_WcT_hi, g_WcT_lo, 512, 512, k & 15, k >> 4);
    } else if (j < 2048) {
        int k = j - 1536;
        do_splitT_block(tile, Wout, g_WoT_hi, g_WoT_lo, 1024, 512, k & 15, k >> 4);
    } else {
        int k = j - 2048;
        int z = k >> 7, rem = k & 127;
        const long s = (long)S_DIM * D_DIM;
        do_splitT_block(tile, context + z * s, g_ctxT_hi + z * s, g_ctxT_lo + z * s,
                        256, 512, rem & 15, rem >> 4);
    }
}

// ---------------- split-bf16 tensor-core GEMM (256 thr, 8 warps, 64x64 tile) ----
#define MMA_BF16(d, a, b)                                                     \
    asm volatile("mma.sync.aligned.m16n8k16.row.col.f32.bf16.bf16.f32 "       \
                 "{%0,%1,%2,%3},{%4,%5,%6,%7},{%8,%9},{%0,%1,%2,%3};"         \
                 : "+f"((d)[0]), "+f"((d)[1]), "+f"((d)[2]), "+f"((d)[3])     \
                 : "r"((a)[0]), "r"((a)[1]), "r"((a)[2]), "r"((a)[3]),        \
                   "r"((b)[0]), "r"((b)[1]))

__global__ __launch_bounds__(256) void gemm_bf16s(
    const __nv_bfloat16* __restrict__ Ahi, const __nv_bfloat16* __restrict__ Alo,
    const __nv_bfloat16* __restrict__ A2hi, const __nv_bfloat16* __restrict__ A2lo,
    const __nv_bfloat16* __restrict__ BThi, const __nv_bfloat16* __restrict__ BTlo,
    float* __restrict__ C,
    __nv_bfloat16* __restrict__ Chi, __nv_bfloat16* __restrict__ Clo,
    int N, int Ka, int Ktot, const float* __restrict__ bias,
    long sA, long sB, long sC)
{
    Ahi  += (long)blockIdx.z * sA;  Alo  += (long)blockIdx.z * sA;
    BThi += (long)blockIdx.z * sB;  BTlo += (long)blockIdx.z * sB;
    if (C)   C   += (long)blockIdx.z * sC;
    if (Chi) { Chi += (long)blockIdx.z * sC; Clo += (long)blockIdx.z * sC; }

    __shared__ __align__(16) __nv_bfloat16 As[2][2][64 * 24];
    __shared__ __align__(16) __nv_bfloat16 Bs[2][2][64 * 24];

    const int tid  = threadIdx.x;
    const int lane = tid & 31;
    const int wid  = tid >> 5;
    const int wm   = wid & 1;
    const int wn   = wid >> 1;
    const int m0   = blockIdx.y * 64;
    const int n0   = blockIdx.x * 64;
    const int g    = lane >> 2;
    const int t    = lane & 3;
    const int arow = tid >> 2;
    const int part = (tid >> 1) & 1;
    const int seg  = tid & 1;

    const int Kb = Ktot - Ka;
    const int KT = Ktot >> 4;

    int4 ra, rb;

#define LDG(kt) {                                                              \
        int gk = (kt) << 4;                                                    \
        const __nv_bfloat16 *ap;                                               \
        if (A2hi && gk >= Ka) {                                                \
            long off = (long)(m0 + arow) * Kb + (gk - Ka) + seg * 8;           \
            ap = (part ? A2lo : A2hi) + off;                                   \
        } else {                                                               \
            long off = (long)(m0 + arow) * Ka + gk + seg * 8;                  \
            ap = (part ? Alo : Ahi) + off;                                     \
        }                                                                      \
        ra = *(const int4*)ap;                                                 \
        long boff = (long)(n0 + arow) * Ktot + gk + seg * 8;                   \
        rb = *(const int4*)((part ? BTlo : BThi) + boff);                      \
    }

#define STS(bf) {                                                              \
        int so = arow * 24 + seg * 8;                                          \
        *(int4*)&As[bf][part][so] = ra;                                        \
        *(int4*)&Bs[bf][part][so] = rb;                                        \
    }

    float acc[2][2][4] = {};

    LDG(0); STS(0);
    __syncthreads();

    for (int kt = 0; kt < KT; kt++) {
        const int buf = kt & 1;
        if (kt + 1 < KT) LDG(kt + 1);

        uint32_t ah[2][4], al[2][4], bh[2][2], bl[2][2];
        const __nv_bfloat16* pah = &As[buf][0][0];
        const __nv_bfloat16* pal = &As[buf][1][0];
        const __nv_bfloat16* pbh = &Bs[buf][0][0];
        const __nv_bfloat16* pbl = &Bs[buf][1][0];

        #pragma unroll
        for (int mi = 0; mi < 2; mi++) {
            int base = (wm * 32 + mi * 16 + g) * 24 + 2 * t;
            ah[mi][0] = *(const uint32_t*)(pah + base);
            ah[mi][1] = *(const uint32_t*)(pah + base + 8 * 24);
            ah[mi][2] = *(const uint32_t*)(pah + base + 8);
            ah[mi][3] = *(const uint32_t*)(pah + base + 8 * 24 + 8);
            al[mi][0] = *(const uint32_t*)(pal + base);
            al[mi][1] = *(const uint32_t*)(pal + base + 8 * 24);
            al[mi][2] = *(const uint32_t*)(pal + base + 8);
            al[mi][3] = *(const uint32_t*)(pal + base + 8 * 24 + 8);
        }
        #pragma unroll
        for (int nj = 0; nj < 2; nj++) {
            int base = (wn * 16 + nj * 8 + g) * 24 + 2 * t;
            bh[nj][0] = *(const uint32_t*)(pbh + base);
            bh[nj][1] = *(const uint32_t*)(pbh + base + 8);
            bl[nj][0] = *(const uint32_t*)(pbl + base);
            bl[nj][1] = *(const uint32_t*)(pbl + base + 8);
        }

        #pragma unroll
        for (int mi = 0; mi < 2; mi++)
            #pragma unroll
            for (int nj = 0; nj < 2; nj++) {
                MMA_BF16(acc[mi][nj], ah[mi], bh[nj]);
                MMA_BF16(acc[mi][nj], ah[mi], bl[nj]);
                MMA_BF16(acc[mi][nj], al[mi], bh[nj]);
            }

        if (kt + 1 < KT) STS(buf ^ 1);
        __syncthreads();
    }

    #pragma unroll
    for (int mi = 0; mi < 2; mi++)
        #pragma unroll
        for (int nj = 0; nj < 2; nj++) {
            int r = m0 + wm * 32 + mi * 16 + g;
            int c = n0 + wn * 16 + nj * 8 + 2 * t;
            float b0 = 0.f, b1 = 0.f;
            if (bias) { b0 = bias[c]; b1 = bias[c + 1]; }
            float v0 = acc[mi][nj][0] + b0, v1 = acc[mi][nj][1] + b1;
            float v2 = acc[mi][nj][2] + b0, v3 = acc[mi][nj][3] + b1;
            if (Chi) {
                __nv_bfloat162 hh0, ll0, hh1, ll1;
                hh0.x = __float2bfloat16(v0); hh0.y = __float2bfloat16(v1);
                ll0.x = __float2bfloat16(v0 - __bfloat162float(hh0.x));
                ll0.y = __float2bfloat16(v1 - __bfloat162float(hh0.y));
                hh1.x = __float2bfloat16(v2); hh1.y = __float2bfloat16(v3);
                ll1.x = __float2bfloat16(v2 - __bfloat162float(hh1.x));
                ll1.y = __float2bfloat16(v3 - __bfloat162float(hh1.y));
                *(__nv_bfloat162*)&Chi[(long)r * N + c]       = hh0;
                *(__nv_bfloat162*)&Clo[(long)r * N + c]       = ll0;
                *(__nv_bfloat162*)&Chi[(long)(r + 8) * N + c] = hh1;
                *(__nv_bfloat162*)&Clo[(long)(r + 8) * N + c] = ll1;
            } else {
                float2 o0; o0.x = v0; o0.y = v1;
                float2 o1; o1.x = v2; o1.y = v3;
                *(float2*)&C[(long)r * N + c]       = o0;
                *(float2*)&C[(long)(r + 8) * N + c] = o1;
            }
        }
#undef LDG
#undef STS
}

// ---------------- score kernel: d-split x2 for occupancy ----------------
// grid (8, 8, 8): z = b*2 + dhalf. Each block reduces 256 d-values into
// g_score2[dhalf]; softmax adds the two halves.
__global__ __launch_bounds__(256) void score_kernel(
    const float* __restrict__ wq, const float* __restrict__ uh,
    const float* __restrict__ v)
{
    const int b     = blockIdx.z >> 1;
    const int dhalf = blockIdx.z & 1;
    const int t0 = blockIdx.y * 32;
    const int s0 = blockIdx.x * 32;
    const int dbase = dhalf * 256;

    __shared__ float wq_s[64][34];
    __shared__ float uh_s[64][34];
    __shared__ float v_s[64];

    const int tid  = threadIdx.x;
    const int tt   = tid >> 4;
    const int ss   = tid & 15;
    const int lrow = tid >> 3;
    const int lcol = (tid & 7) * 8;

    const float* wq_b = wq + ((long)b * T_DIM + t0) * D_DIM + dbase;
    const float* uh_b = uh + ((long)b * S_DIM + s0) * D_DIM + dbase;

    float acc00 = 0.f, acc01 = 0.f, acc10 = 0.f, acc11 = 0.f;

    for (int d0 = 0; d0 < 256; d0 += 64) {
        float4 w0 = *(const float4*)&wq_b[(long)lrow * D_DIM + d0 + lcol];
        float4 w1 = *(const float4*)&wq_b[(long)lrow * D_DIM + d0 + lcol + 4];
        float4 u0 = *(const float4*)&uh_b[(long)lrow * D_DIM + d0 + lcol];
        float4 u1 = *(const float4*)&uh_b[(long)lrow * D_DIM + d0 + lcol + 4];

        wq_s[lcol + 0][lrow] = w0.x; wq_s[lcol + 1][lrow] = w0.y;
        wq_s[lcol + 2][lrow] = w0.z; wq_s[lcol + 3][lrow] = w0.w;
        wq_s[lcol + 4][lrow] = w1.x; wq_s[lcol + 5][lrow] = w1.y;
        wq_s[lcol + 6][lrow] = w1.z; wq_s[lcol + 7][lrow] = w1.w;
        uh_s[lcol + 0][lrow] = u0.x; uh_s[lcol + 1][lrow] = u0.y;
        uh_s[lcol + 2][lrow] = u0.z; uh_s[lcol + 3][lrow] = u0.w;
        uh_s[lcol + 4][lrow] = u1.x; uh_s[lcol + 5][lrow] = u1.y;
        uh_s[lcol + 6][lrow] = u1.z; uh_s[lcol + 7][lrow] = u1.w;
        if (tid < 16) *(float4*)&v_s[tid * 4] = *(const float4*)&v[dbase + d0 + tid * 4];
        __syncthreads();

        #pragma unroll 16
        for (int d = 0; d < 64; d++) {
            float2 a = *(const float2*)&wq_s[d][tt * 2];
            float2 u = *(const float2*)&uh_s[d][ss * 2];
            float vd = v_s[d];
            acc00 = fmaf(vd, tanh_fast(a.x + u.x), acc00);
            acc01 = fmaf(vd, tanh_fast(a.x + u.y), acc01);
            acc10 = fmaf(vd, tanh_fast(a.y + u.x), acc10);
            acc11 = fmaf(vd, tanh_fast(a.y + u.y), acc11);
        }
        __syncthreads();
    }

    float* sp = g_score2[dhalf];
    long base = ((long)b * T_DIM + t0 + tt * 2) * S_DIM + s0 + ss * 2;
    sp[base]             = acc00;
    sp[base + 1]         = acc01;
    sp[base + S_DIM]     = acc10;
    sp[base + S_DIM + 1] = acc11;
}

// ---------------- masked softmax (sums d-halves) + fused attn hi/lo split --------
__device__ __forceinline__ void wr_split2(
    __nv_bfloat16* hp, __nv_bfloat16* lp, int c, float a, float b)
{
    __nv_bfloat16 h0 = __float2bfloat16(a);
    __nv_bfloat16 h1 = __float2bfloat16(b);
    __nv_bfloat162 hh; hh.x = h0; hh.y = h1;
    __nv_bfloat162 ll;
    ll.x = __float2bfloat16(a - __bfloat162float(h0));
    ll.y = __float2bfloat16(b - __bfloat162float(h1));
    *(__nv_bfloat162*)(hp + c) = hh;
    *(__nv_bfloat162*)(lp + c) = ll;
}

__global__ __launch_bounds__(256) void softmax_kernel(
    const int* __restrict__ mask,
    __nv_bfloat16* __restrict__ at_hi, __nv_bfloat16* __restrict__ at_lo,
    float* __restrict__ attn_out)
{
    const int lane = threadIdx.x & 31;
    const int w    = threadIdx.x >> 5;
    const int row  = blockIdx.x * 8 + w;    // b*T + t
    const int b    = row >> 8;              // T = 256

    const float4* sr0 = (const float4*)(g_score2[0] + (long)row * S_DIM);
    const float4* sr1 = (const float4*)(g_score2[1] + (long)row * S_DIM);
    float4 p0 = sr0[lane], q0 = sr1[lane];
    float4 p1 = sr0[lane + 32], q1 = sr1[lane + 32];
    float4 x0, x1;
    x0.x = p0.x + q0.x; x0.y = p0.y + q0.y; x0.z = p0.z + q0.z; x0.w = p0.w + q0.w;
    x1.x = p1.x + q1.x; x1.y = p1.y + q1.y; x1.z = p1.z + q1.z; x1.w = p1.w + q1.w;

    float m = fmaxf(fmaxf(fmaxf(x0.x, x0.y), fmaxf(x0.z, x0.w)),
                    fmaxf(fmaxf(x1.x, x1.y), fmaxf(x1.z, x1.w)));
    #pragma unroll
    for (int o = 16; o > 0; o >>= 1) m = fmaxf(m, __shfl_xor_sync(0xffffffffu, m, o));

    const int4* mp = (const int4*)(mask + b * S_DIM);
    int4 k0 = mp[lane];
    int4 k1 = mp[lane + 32];

    float4 e0, e1;
    e0.x = __expf(x0.x - m) * (1.0f - (float)k0.x);
    e0.y = __expf(x0.y - m) * (1.0f - (float)k0.y);
    e0.z = __expf(x0.z - m) * (1.0f - (float)k0.z);
    e0.w = __expf(x0.w - m) * (1.0f - (float)k0.w);
    e1.x = __expf(x1.x - m) * (1.0f - (float)k1.x);
    e1.y = __expf(x1.y - m) * (1.0f - (float)k1.y);
    e1.z = __expf(x1.z - m) * (1.0f - (float)k1.z);
    e1.w = __expf(x1.w - m) * (1.0f - (float)k1.w);

    float sum = e0.x + e0.y + e0.z + e0.w + e1.x + e1.y + e1.z + e1.w;
    #pragma unroll
    for (int o = 16; o > 0; o >>= 1) sum += __shfl_xor_sync(0xffffffffu, sum, o);

    float inv = 1.0f / sum;
    e0.x *= inv; e0.y *= inv; e0.z *= inv; e0.w *= inv;
    e1.x *= inv; e1.y *= inv; e1.z *= inv; e1.w *= inv;

    __nv_bfloat16* hp = at_hi + (long)row * S_DIM;
    __nv_bfloat16* lp = at_lo + (long)row * S_DIM;
    wr_split2(hp, lp, 4 * lane,       e0.x, e0.y);
    wr_split2(hp, lp, 4 * lane + 2,   e0.z, e0.w);
    wr_split2(hp, lp, 128 + 4 * lane, e1.x, e1.y);
    wr_split2(hp, lp, 130 + 4 * lane, e1.z, e1.w);

    if (attn_out) {
        float4* ao = (float4*)(attn_out + (long)row * S_DIM);
        ao[lane]      = e0;
        ao[lane + 32] = e1;
    }
}

// ---------------- launch ----------------
extern "C" void kernel_launch(void* const* d_in, const int* in_sizes, int n_in,
                              void* d_out, int out_size)
{
    const float* output  = (const float*)d_in[0];
    const float* context = (const float*)d_in[1];
    const int*   mask    = (const int*)d_in[2];
    const float* Wq      = (const float*)d_in[3];
    const float* bq      = (const float*)d_in[4];
    const float* Wc      = (const float*)d_in[5];
    const float* v       = (const float*)d_in[6];
    const float* Wout    = (const float*)d_in[7];
    const float* bout    = (const float*)d_in[8];

    float *wq, *uh;
    cudaGetSymbolAddress((void**)&wq, g_wq);
    cudaGetSymbolAddress((void**)&uh, g_uh);

    __nv_bfloat16 *out_hi, *out_lo, *ctx_hi, *ctx_lo, *ctxT_hi, *ctxT_lo;
    __nv_bfloat16 *WqT_hi, *WqT_lo, *WcT_hi, *WcT_lo, *WoT_hi, *WoT_lo;
    __nv_bfloat16 *at_hi, *at_lo, *mx_hi, *mx_lo;
    cudaGetSymbolAddress((void**)&out_hi,  g_out_hi);
    cudaGetSymbolAddress((void**)&out_lo,  g_out_lo);
    cudaGetSymbolAddress((void**)&ctx_hi,  g_ctx_hi);
    cudaGetSymbolAddress((void**)&ctx_lo,  g_ctx_lo);
    cudaGetSymbolAddress((void**)&ctxT_hi, g_ctxT_hi);
    cudaGetSymbolAddress((void**)&ctxT_lo, g_ctxT_lo);
    cudaGetSymbolAddress((void**)&WqT_hi,  g_WqT_hi);
    cudaGetSymbolAddress((void**)&WqT_lo,  g_WqT_lo);
    cudaGetSymbolAddress((void**)&WcT_hi,  g_WcT_hi);
    cudaGetSymbolAddress((void**)&WcT_lo,  g_WcT_lo);
    cudaGetSymbolAddress((void**)&WoT_hi,  g_WoT_hi);
    cudaGetSymbolAddress((void**)&WoT_lo,  g_WoT_lo);
    cudaGetSymbolAddress((void**)&at_hi,   g_at_hi);
    cudaGetSymbolAddress((void**)&at_lo,   g_at_lo);
    cudaGetSymbolAddress((void**)&mx_hi,   g_mx_hi);
    cudaGetSymbolAddress((void**)&mx_lo,   g_mx_lo);

    float* out = (float*)d_out;
    const int out_elems  = B_DIM * T_DIM * D_DIM;   // 524288
    const int attn_elems = B_DIM * T_DIM * S_DIM;   // 262144
    float* attn_out = (out_size >= out_elems + attn_elems) ? (out + out_elems) : nullptr;

    const long sCtxT = (long)S_DIM * D_DIM;

    // 1) all staging in one wide launch
    stage_all<<<2560, 256>>>(output, context, Wq, Wc, Wout);

    // 2) wq GEMM (s0) and uh GEMM (s1) concurrently
    cudaEventRecord(evFork, 0);
    cudaStreamWaitEvent(s1, evFork, 0);

    gemm_bf16s<<<dim3(8, 16, 1), 256>>>(out_hi, out_lo, nullptr, nullptr,
                                        WqT_hi, WqT_lo, wq, nullptr, nullptr,
                                        512, 512, 512, bq, 0, 0, 0);
    gemm_bf16s<<<dim3(8, 16, 1), 256, 0, s1>>>(ctx_hi, ctx_lo, nullptr, nullptr,
                                               WcT_hi, WcT_lo, uh, nullptr, nullptr,
                                               512, 512, 512, nullptr, 0, 0, 0);
    cudaEventRecord(ev1, s1);
    cudaStreamWaitEvent(0, ev1, 0);

    // 3) score (d-split x2) -> softmax -> mix GEMM -> final GEMM
    score_kernel<<<dim3(8, 8, 8), 256>>>(wq, uh, v);
    softmax_kernel<<<128, 256>>>(mask, at_hi, at_lo, attn_out);
    gemm_bf16s<<<dim3(8, 4, 4), 256>>>(at_hi, at_lo, nullptr, nullptr,
                                       ctxT_hi, ctxT_lo, nullptr, mx_hi, mx_lo,
                                       512, 256, 256, nullptr,
                                       (long)T_DIM * S_DIM, sCtxT, (long)T_DIM * D_DIM);
    gemm_bf16s<<<dim3(8, 16, 1), 256>>>(mx_hi, mx_lo, out_hi, out_lo,
                                        WoT_hi, WoT_lo, out, nullptr, nullptr,
                                        512, 512, 1024, bout, 0, 0, 0);
}